// round 12
// baseline (speedup 1.0000x reference)
#include <cuda_runtime.h>
#include <cuda_bf16.h>
#include <cstdint>

// CrossAttentionFusion: B=4, S2_CH=256, DEM_CH=64, OUT_CH=256, H=W=64, N=4096
#define BB 4
#define CS 256
#define CD 64
#define CO 256
#define NN 4096
#define SCALE 0.0625f

// Scratch (device globals: allocation-free rule)
__device__ float         g_Qf[(size_t)BB * CO * NN];
__device__ float         g_Kf[(size_t)BB * CO * NN];
__device__ float         g_Vf[(size_t)BB * CO * NN];
__device__ __nv_bfloat16 g_Qt[(size_t)BB * NN * CO];   // Q^T bf16 [b][j][c] (scale folded)
__device__ __nv_bfloat16 g_Kt[(size_t)BB * NN * CO];   // K^T bf16 [b][i][c]
__device__ __nv_bfloat16 g_Vb[(size_t)BB * CO * NN];   // V' = V/R bf16 [b][c][i]
__device__ __nv_bfloat16 g_E [(size_t)BB * NN * NN];   // exp(logits) bf16 [b][i][j]
__device__ float         g_R [(size_t)BB * NN];        // row sums of E

// ===========================================================================
// helpers
// ===========================================================================
__device__ __forceinline__ uint32_t smem_u32(const void* p) {
    uint32_t a;
    asm("{ .reg .u64 t; cvta.to.shared.u64 t, %1; cvt.u32.u64 %0, t; }"
        : "=r"(a) : "l"(p));
    return a;
}

#define CP16(dst, src) \
    asm volatile("cp.async.cg.shared.global [%0], [%1], 16;" \
                 :: "r"(dst), "l"(src))
#define CP_COMMIT() asm volatile("cp.async.commit_group;" ::: "memory")
#define CP_WAIT1()  asm volatile("cp.async.wait_group 1;" ::: "memory")
#define CP_WAIT0()  asm volatile("cp.async.wait_group 0;" ::: "memory")

#define LDSM4(r0, r1, r2, r3, addr) \
    asm volatile("ldmatrix.sync.aligned.m8n8.x4.shared.b16 {%0,%1,%2,%3}, [%4];" \
                 : "=r"(r0), "=r"(r1), "=r"(r2), "=r"(r3) : "r"(addr))
#define LDSM2T(r0, r1, addr) \
    asm volatile("ldmatrix.sync.aligned.m8n8.x2.trans.shared.b16 {%0,%1}, [%2];" \
                 : "=r"(r0), "=r"(r1) : "r"(addr))

#define MMA_BF16(d, av, bv) \
    asm volatile("mma.sync.aligned.m16n8k16.row.col.f32.bf16.bf16.f32 " \
                 "{%0,%1,%2,%3}, {%4,%5,%6,%7}, {%8,%9}, {%0,%1,%2,%3};" \
                 : "+f"((d)[0]), "+f"((d)[1]), "+f"((d)[2]), "+f"((d)[3]) \
                 : "r"((av)[0]), "r"((av)[1]), "r"((av)[2]), "r"((av)[3]), \
                   "r"((bv)[0]), "r"((bv)[1]))

__device__ __forceinline__ uint2 pack4bf(float a, float b, float c, float d) {
    __nv_bfloat162 lo = __floats2bfloat162_rn(a, b);
    __nv_bfloat162 hi = __floats2bfloat162_rn(c, d);
    uint2 r;
    r.x = *(uint32_t*)&lo;
    r.y = *(uint32_t*)&hi;
    return r;
}

// ===========================================================================
// s_mma_d: E[b,i,j] = exp( sum_c Kt[b,i,c] * Qt[b,j,c] )   (scale in Qt)
// CTA 128(i) x 128(j), 8 warps (warp tile 64x32), k-chunks of 32, 2-stage.
// A-fragments via ldmatrix.x4; B-fragments via proven direct b32 loads.
// ===========================================================================
#define SA_STRIDE 80                       // 32 bf16 (64B) + 16B pad
#define SA_BYTES  (128 * SA_STRIDE)        // 10240
#define S_STAGE   (2 * SA_BYTES)

__global__ void __launch_bounds__(256, 1)
s_mma_d(const __nv_bfloat16* __restrict__ Kt,
        const __nv_bfloat16* __restrict__ Qt,
        __nv_bfloat16* __restrict__ E)
{
    __shared__ __align__(16) char sm[2 * S_STAGE];   // 40 KB
    const int tid = threadIdx.x, lane = tid & 31, wid = tid >> 5;
    const int b = blockIdx.z, i0 = blockIdx.y * 128, j0 = blockIdx.x * 128;
    const int wm = wid & 1, wn = wid >> 1;
    const int qr = lane >> 2;
    const int qk = (lane & 3) * 2;

    const __nv_bfloat16* Ag = Kt + ((size_t)b * NN + i0) * CS;
    const __nv_bfloat16* Bg = Qt + ((size_t)b * NN + j0) * CS;
    const uint32_t sbase = smem_u32(sm);

    const int crow = tid >> 2, cseg = tid & 3;

    auto issue = [&](int ch, int st) {
        uint32_t sA = sbase + st * S_STAGE;
        uint32_t sB = sA + SA_BYTES;
        const __nv_bfloat16* a0 = Ag + ch * 32;
        const __nv_bfloat16* b0 = Bg + ch * 32;
        #pragma unroll
        for (int t = 0; t < 2; t++) {
            int row = crow + t * 64;
            uint32_t off = (uint32_t)(row * SA_STRIDE + cseg * 16);
            CP16(sA + off, a0 + (size_t)row * CS + cseg * 8);
            CP16(sB + off, b0 + (size_t)row * CS + cseg * 8);
        }
        CP_COMMIT();
    };

    float acc[4][4][4] = {};
    issue(0, 0);
    issue(1, 1);

    #pragma unroll 1
    for (int ch = 0; ch < 8; ch++) {
        const int st = ch & 1;
        if (ch == 7) CP_WAIT0(); else CP_WAIT1();
        __syncthreads();
        const uint32_t sA32 = sbase + st * S_STAGE;
        const char* pB = sm + st * S_STAGE + SA_BYTES;
        #pragma unroll
        for (int ks = 0; ks < 2; ks++) {
            const int kbyte = ks * 32 + qk * 2;
            uint32_t a[4][4], bb[4][2];
            #pragma unroll
            for (int mf = 0; mf < 4; mf++) {
                // ldmatrix x4: lanes 0-15 -> rows (m), lanes 16-31 -> +16B (k8-15)
                int row = wm * 64 + mf * 16 + (lane & 15);
                uint32_t ad = sA32 + (uint32_t)(row * SA_STRIDE + (lane >> 4) * 16
                                                + ks * 32);
                LDSM4(a[mf][0], a[mf][1], a[mf][2], a[mf][3], ad);
            }
            #pragma unroll
            for (int nf = 0; nf < 4; nf++) {
                int n = wn * 32 + nf * 8 + qr;
                const char* base = pB + n * SA_STRIDE + kbyte;
                bb[nf][0] = *(const uint32_t*)(base);
                bb[nf][1] = *(const uint32_t*)(base + 16);
            }
            #pragma unroll
            for (int mf = 0; mf < 4; mf++)
                #pragma unroll
                for (int nf = 0; nf < 4; nf++)
                    MMA_BF16(acc[mf][nf], a[mf], bb[nf]);
        }
        __syncthreads();
        if (ch + 2 < 8) issue(ch + 2, st);
    }

    const int qc = (lane & 3) * 2;
    __nv_bfloat16* Eb = E + ((size_t)b * NN + i0) * NN + j0;
    #pragma unroll
    for (int mf = 0; mf < 4; mf++) {
        #pragma unroll
        for (int nf = 0; nf < 4; nf++) {
            int r = wm * 64 + mf * 16 + qr;
            int c = wn * 32 + nf * 8 + qc;
            *(__nv_bfloat162*)&Eb[(size_t)r * NN + c] =
                __floats2bfloat162_rn(__expf(acc[mf][nf][0]), __expf(acc[mf][nf][1]));
            *(__nv_bfloat162*)&Eb[(size_t)(r + 8) * NN + c] =
                __floats2bfloat162_rn(__expf(acc[mf][nf][2]), __expf(acc[mf][nf][3]));
        }
    }
}

// ===========================================================================
// rowsum: R[b,i] = sum_j E[b,i,j]   (f32 accumulate from stored bf16 E)
// ===========================================================================
__global__ void rowsum_kernel(const __nv_bfloat16* __restrict__ E,
                              float* __restrict__ R)
{
    const int i = blockIdx.x, b = blockIdx.y;
    const uint4* row = (const uint4*)(E + ((size_t)b * NN + i) * NN);
    const int tid = threadIdx.x;
    __shared__ float red[8];

    float s = 0.0f;
    #pragma unroll
    for (int u = 0; u < 2; u++) {
        uint4 v = row[tid + u * 256];
        uint32_t w[4] = {v.x, v.y, v.z, v.w};
        #pragma unroll
        for (int q = 0; q < 4; q++) {
            float2 f = __bfloat1622float2(*(const __nv_bfloat162*)&w[q]);
            s += f.x + f.y;
        }
    }
    #pragma unroll
    for (int off = 16; off > 0; off >>= 1)
        s += __shfl_xor_sync(0xFFFFFFFFu, s, off);
    if ((tid & 31) == 0) red[tid >> 5] = s;
    __syncthreads();
    if (tid == 0) {
        float t = 0.0f;
        #pragma unroll
        for (int w2 = 0; w2 < 8; w2++) t += red[w2];
        R[(size_t)b * NN + i] = t;
    }
}

// ===========================================================================
// vscale: Vb[b,c,i] = bf16( Vf[b,c,i] / R[b,i] )
// ===========================================================================
__global__ void vscale_kernel(const float* __restrict__ Vf,
                              const float* __restrict__ R,
                              __nv_bfloat16* __restrict__ Vb)
{
    size_t idx = ((size_t)blockIdx.x * 256 + threadIdx.x) * 4;
    int i = (int)(idx & (NN - 1));
    int b = (int)(idx >> 20);                 // CO*NN = 2^20
    float4 v = *(const float4*)&Vf[idx];
    float4 rr = *(const float4*)&R[(size_t)b * NN + i];
    *(uint2*)&Vb[idx] = pack4bf(v.x / rr.x, v.y / rr.y, v.z / rr.z, v.w / rr.w);
}

// ===========================================================================
// out_mma_d: out[b,c,j] = sum_i V'[b,c,i]*E[b,i,j] + xs2
// 256 threads, CTA 128(c) x 128(j).
// A-fragments via ldmatrix.x4; B-fragments via ldmatrix.x2.trans (R10-proven).
// ===========================================================================
#define SBO_STRIDE 272                     // 128 bf16 (256B) + 16B pad
#define SBO_BYTES  (32 * SBO_STRIDE)       // 8704
#define O_STAGE    (SA_BYTES + SBO_BYTES)  // 18944

__global__ void __launch_bounds__(256, 1)
out_mma_d(const __nv_bfloat16* __restrict__ V,
          const __nv_bfloat16* __restrict__ E,
          const float* __restrict__ xs2,
          float* __restrict__ out)
{
    __shared__ __align__(16) char sm[2 * O_STAGE];   // 37.9 KB
    const int tid = threadIdx.x, lane = tid & 31, wid = tid >> 5;
    const int b = blockIdx.z, c0 = blockIdx.y * 128, j0 = blockIdx.x * 128;
    const int wm = wid & 1, wn = wid >> 1;
    const int qr = lane >> 2;
    const int ln = lane & 15;

    const __nv_bfloat16* Ag = V + ((size_t)b * CO + c0) * NN;
    const __nv_bfloat16* Bg = E + (size_t)b * NN * NN + j0;
    const uint32_t sbase = smem_u32(sm);

    const int arow = tid >> 2, aseg = tid & 3;
    const int brow = tid >> 4, bseg = tid & 15;

    auto issue = [&](int ch, int st) {
        uint32_t sA = sbase + st * O_STAGE;
        uint32_t sB = sA + SA_BYTES;
        const __nv_bfloat16* a0 = Ag + ch * 32;
        const __nv_bfloat16* b0 = Bg + (size_t)(ch * 32) * NN;
        #pragma unroll
        for (int t = 0; t < 2; t++) {
            int ra = arow + t * 64;
            CP16(sA + (uint32_t)(ra * SA_STRIDE + aseg * 16),
                 a0 + (size_t)ra * NN + aseg * 8);
            int rb = brow + t * 16;
            CP16(sB + (uint32_t)(rb * SBO_STRIDE + bseg * 16),
                 b0 + (size_t)rb * NN + bseg * 8);
        }
        CP_COMMIT();
    };

    float acc[4][4][4] = {};
    issue(0, 0);
    issue(1, 1);

    const int NCH = NN / 32;   // 128
    #pragma unroll 1
    for (int ch = 0; ch < NCH; ch++) {
        const int st = ch & 1;
        if (ch == NCH - 1) CP_WAIT0(); else CP_WAIT1();
        __syncthreads();
        const uint32_t sA32 = sbase + st * O_STAGE;
        const uint32_t sB32 = sA32 + SA_BYTES;
        #pragma unroll
        for (int ks = 0; ks < 2; ks++) {
            // ldmatrix.trans row addresses: rows k = ks*16 + ln (lanes 0-15)
            const uint32_t brow_addr = sB32 + (uint32_t)((ks * 16 + ln) * SBO_STRIDE
                                                         + wn * 64);
            uint32_t a[4][4], bb[4][2];
            #pragma unroll
            for (int mf = 0; mf < 4; mf++) {
                int row = wm * 64 + mf * 16 + ln;
                uint32_t ad = sA32 + (uint32_t)(row * SA_STRIDE + (lane >> 4) * 16
                                                + ks * 32);
                LDSM4(a[mf][0], a[mf][1], a[mf][2], a[mf][3], ad);
            }
            #pragma unroll
            for (int nf = 0; nf < 4; nf++)
                LDSM2T(bb[nf][0], bb[nf][1], brow_addr + nf * 16);
            #pragma unroll
            for (int mf = 0; mf < 4; mf++)
                #pragma unroll
                for (int nf = 0; nf < 4; nf++)
                    MMA_BF16(acc[mf][nf], a[mf], bb[nf]);
        }
        __syncthreads();
        if (ch + 2 < NCH) issue(ch + 2, st);
    }

    const int qc = (lane & 3) * 2;
    const float* Xb = xs2 + ((size_t)b * CO + c0) * NN + j0;
    float* Ob = out + ((size_t)b * CO + c0) * NN + j0;
    #pragma unroll
    for (int mf = 0; mf < 4; mf++) {
        #pragma unroll
        for (int nf = 0; nf < 4; nf++) {
            int r = wm * 64 + mf * 16 + qr;
            int c = wn * 32 + nf * 8 + qc;
            float2 x0 = *(const float2*)&Xb[(size_t)r * NN + c];
            float2 x1 = *(const float2*)&Xb[(size_t)(r + 8) * NN + c];
            *(float2*)&Ob[(size_t)r * NN + c] =
                make_float2(acc[mf][nf][0] + x0.x, acc[mf][nf][1] + x0.y);
            *(float2*)&Ob[(size_t)(r + 8) * NN + c] =
                make_float2(acc[mf][nf][2] + x1.x, acc[mf][nf][3] + x1.y);
        }
    }
}

// ===========================================================================
// Projection (R1-proven, f32 out)
// ===========================================================================
template <int CIN>
__global__ void proj_kernel(const float* __restrict__ X,
                            const float* __restrict__ W,
                            const float* __restrict__ bias,
                            float* __restrict__ Y)
{
    const int b  = blockIdx.z;
    const int j0 = blockIdx.x * 64;
    const int m0 = blockIdx.y * 64;

    __shared__ float As[16][68];
    __shared__ float Bs[16][68];

    const int tid = threadIdx.x;
    const int tx = tid & 15;
    const int ty = tid >> 4;

    const float* Xb = X + (size_t)b * CIN * NN;
    float acc[4][4] = {};

    for (int k0 = 0; k0 < CIN; k0 += 16) {
        {
            int m  = tid >> 2;
            int kq = (tid & 3) * 4;
            float4 w4 = *(const float4*)&W[(size_t)(m0 + m) * CIN + k0 + kq];
            As[kq + 0][m] = w4.x; As[kq + 1][m] = w4.y;
            As[kq + 2][m] = w4.z; As[kq + 3][m] = w4.w;
        }
        {
            int k  = tid >> 4;
            int jq = (tid & 15) * 4;
            *(float4*)&Bs[k][jq] = *(const float4*)&Xb[(size_t)(k0 + k) * NN + j0 + jq];
        }
        __syncthreads();
        #pragma unroll
        for (int k = 0; k < 16; k++) {
            float4 a4 = *(const float4*)&As[k][ty * 4];
            float4 b4 = *(const float4*)&Bs[k][tx * 4];
            float a[4] = {a4.x, a4.y, a4.z, a4.w};
            float bv[4] = {b4.x, b4.y, b4.z, b4.w};
            #pragma unroll
            for (int i = 0; i < 4; i++)
                #pragma unroll
                for (int j = 0; j < 4; j++)
                    acc[i][j] += a[i] * bv[j];
        }
        __syncthreads();
    }

    float* Yb = Y + (size_t)b * CO * NN;
    #pragma unroll
    for (int i = 0; i < 4; i++) {
        int m = m0 + ty * 4 + i;
        float bs = bias[m];
        *(float4*)&Yb[(size_t)m * NN + j0 + tx * 4] =
            make_float4(acc[i][0] + bs, acc[i][1] + bs,
                        acc[i][2] + bs, acc[i][3] + bs);
    }
}

// ===========================================================================
// Tiled transpose + scale + bf16: Yt[b][n][c] = bf16(X[b][c][n] * scale)
// ===========================================================================
__global__ void transpose_scale_bf16(const float* __restrict__ X,
                                     __nv_bfloat16* __restrict__ Yt,
                                     float scale)
{
    __shared__ float t[32][33];
    const int b  = blockIdx.z;
    const int n0 = blockIdx.x * 32;
    const int c0 = blockIdx.y * 32;
    const int tx = threadIdx.x, ty = threadIdx.y;

    const float* Xb = X + ((size_t)b * CO + c0) * NN + n0;
    #pragma unroll
    for (int k = 0; k < 4; k++) {
        int r = ty + k * 8;
        t[r][tx] = Xb[(size_t)r * NN + tx];
    }
    __syncthreads();

    __nv_bfloat16* Yb = Yt + ((size_t)b * NN + n0) * CO + c0;
    #pragma unroll
    for (int k = 0; k < 4; k++) {
        int r = ty + k * 8;
        Yb[(size_t)r * CO + tx] = __float2bfloat16(t[tx][r] * scale);
    }
}

// ===========================================================================
extern "C" void kernel_launch(void* const* d_in, const int* in_sizes, int n_in,
                              void* d_out, int out_size)
{
    const float* x_s2  = (const float*)d_in[0];
    const float* x_dem = (const float*)d_in[1];
    const float* Wq    = (const float*)d_in[2];
    const float* bq    = (const float*)d_in[3];
    const float* Wk    = (const float*)d_in[4];
    const float* bk    = (const float*)d_in[5];
    const float* Wv    = (const float*)d_in[6];
    const float* bv    = (const float*)d_in[7];
    float* out = (float*)d_out;

    float *Qf, *Kf, *Vf, *Rp;
    __nv_bfloat16 *Qt, *Kt, *Vb, *Ep;
    cudaGetSymbolAddress((void**)&Qf, g_Qf);
    cudaGetSymbolAddress((void**)&Kf, g_Kf);
    cudaGetSymbolAddress((void**)&Vf, g_Vf);
    cudaGetSymbolAddress((void**)&Qt, g_Qt);
    cudaGetSymbolAddress((void**)&Kt, g_Kt);
    cudaGetSymbolAddress((void**)&Vb, g_Vb);
    cudaGetSymbolAddress((void**)&Ep, g_E);
    cudaGetSymbolAddress((void**)&Rp, g_R);

    dim3 blk(256);
    dim3 grid_proj(NN / 64, CO / 64, BB);
    proj_kernel<CS><<<grid_proj, blk>>>(x_s2,  Wq, bq, Qf);
    proj_kernel<CD><<<grid_proj, blk>>>(x_dem, Wk, bk, Kf);
    proj_kernel<CD><<<grid_proj, blk>>>(x_dem, Wv, bv, Vf);

    dim3 grid_tr(NN / 32, CO / 32, BB);
    dim3 blk_tr(32, 8);
    transpose_scale_bf16<<<grid_tr, blk_tr>>>(Qf, Qt, SCALE);
    transpose_scale_bf16<<<grid_tr, blk_tr>>>(Kf, Kt, 1.0f);

    s_mma_d<<<dim3(NN / 128, NN / 128, BB), blk>>>(Kt, Qt, Ep);

    rowsum_kernel<<<dim3(NN, BB), blk>>>(Ep, Rp);

    vscale_kernel<<<(unsigned)((size_t)BB * CO * NN / 1024), 256>>>(Vf, Rp, Vb);

    out_mma_d<<<dim3(NN / 128, CO / 128, BB), blk>>>(Vb, Ep, x_s2, out);
}

// round 13
// speedup vs baseline: 1.0985x; 1.0985x over previous
#include <cuda_runtime.h>
#include <cuda_bf16.h>
#include <cstdint>

// CrossAttentionFusion: B=4, S2_CH=256, DEM_CH=64, OUT_CH=256, H=W=64, N=4096
#define BB 4
#define CS 256
#define CD 64
#define CO 256
#define NN 4096
#define SCALE 0.0625f

// Scratch (device globals: allocation-free rule)
__device__ float         g_Qf[(size_t)BB * CO * NN];
__device__ float         g_Kf[(size_t)BB * CO * NN];
__device__ float         g_Vf[(size_t)BB * CO * NN];
__device__ __nv_bfloat16 g_Qt[(size_t)BB * NN * CO];   // Q^T bf16 [b][j][c] (scale folded)
__device__ __nv_bfloat16 g_Kt[(size_t)BB * NN * CO];   // K^T bf16 [b][i][c]
__device__ __nv_bfloat16 g_Vb[(size_t)BB * CO * NN];   // V' = V/R bf16 [b][c][i]
__device__ __nv_bfloat16 g_E [(size_t)BB * NN * NN];   // exp(logits) bf16 [b][i][j]
__device__ float         g_R [(size_t)BB * NN];        // row sums of E

// ===========================================================================
// helpers
// ===========================================================================
__device__ __forceinline__ uint32_t smem_u32(const void* p) {
    uint32_t a;
    asm("{ .reg .u64 t; cvta.to.shared.u64 t, %1; cvt.u32.u64 %0, t; }"
        : "=r"(a) : "l"(p));
    return a;
}

#define CP16(dst, src) \
    asm volatile("cp.async.cg.shared.global [%0], [%1], 16;" \
                 :: "r"(dst), "l"(src))
#define CP_COMMIT() asm volatile("cp.async.commit_group;" ::: "memory")
#define CP_WAITN(n) asm volatile("cp.async.wait_group %0;" :: "n"(n) : "memory")

#define LDSM2T(r0, r1, addr) \
    asm volatile("ldmatrix.sync.aligned.m8n8.x2.trans.shared.b16 {%0,%1}, [%2];" \
                 : "=r"(r0), "=r"(r1) : "r"(addr))

#define MMA_BF16(d, av, bv) \
    asm volatile("mma.sync.aligned.m16n8k16.row.col.f32.bf16.bf16.f32 " \
                 "{%0,%1,%2,%3}, {%4,%5,%6,%7}, {%8,%9}, {%0,%1,%2,%3};" \
                 : "+f"((d)[0]), "+f"((d)[1]), "+f"((d)[2]), "+f"((d)[3]) \
                 : "r"((av)[0]), "r"((av)[1]), "r"((av)[2]), "r"((av)[3]), \
                   "r"((bv)[0]), "r"((bv)[1]))

__device__ __forceinline__ uint2 pack4bf(float a, float b, float c, float d) {
    __nv_bfloat162 lo = __floats2bfloat162_rn(a, b);
    __nv_bfloat162 hi = __floats2bfloat162_rn(c, d);
    uint2 r;
    r.x = *(uint32_t*)&lo;
    r.y = *(uint32_t*)&hi;
    return r;
}

// ===========================================================================
// s_mma_d: E[b,i,j] = exp( sum_c Kt[b,i,c] * Qt[b,j,c] )   (scale in Qt)
// CTA 128(i) x 128(j), 8 warps (warp tile 64x32), k-chunks of 32, 2-stage.
// (R10-proven: direct b32 fragment loads for A and B.)
// ===========================================================================
#define SA_STRIDE 80                       // 32 bf16 (64B) + 16B pad
#define SA_BYTES  (128 * SA_STRIDE)        // 10240
#define S_STAGE   (2 * SA_BYTES)

__global__ void __launch_bounds__(256, 1)
s_mma_d(const __nv_bfloat16* __restrict__ Kt,
        const __nv_bfloat16* __restrict__ Qt,
        __nv_bfloat16* __restrict__ E)
{
    __shared__ __align__(16) char sm[2 * S_STAGE];   // 40 KB
    const int tid = threadIdx.x, lane = tid & 31, wid = tid >> 5;
    const int b = blockIdx.z, i0 = blockIdx.y * 128, j0 = blockIdx.x * 128;
    const int wm = wid & 1, wn = wid >> 1;
    const int qr = lane >> 2;
    const int qk = (lane & 3) * 2;

    const __nv_bfloat16* Ag = Kt + ((size_t)b * NN + i0) * CS;
    const __nv_bfloat16* Bg = Qt + ((size_t)b * NN + j0) * CS;
    const uint32_t sbase = smem_u32(sm);

    const int crow = tid >> 2, cseg = tid & 3;

    auto issue = [&](int ch, int st) {
        uint32_t sA = sbase + st * S_STAGE;
        uint32_t sB = sA + SA_BYTES;
        const __nv_bfloat16* a0 = Ag + ch * 32;
        const __nv_bfloat16* b0 = Bg + ch * 32;
        #pragma unroll
        for (int t = 0; t < 2; t++) {
            int row = crow + t * 64;
            uint32_t off = (uint32_t)(row * SA_STRIDE + cseg * 16);
            CP16(sA + off, a0 + (size_t)row * CS + cseg * 8);
            CP16(sB + off, b0 + (size_t)row * CS + cseg * 8);
        }
        CP_COMMIT();
    };

    float acc[4][4][4] = {};
    issue(0, 0);
    issue(1, 1);

    #pragma unroll 1
    for (int ch = 0; ch < 8; ch++) {
        const int st = ch & 1;
        if (ch == 7) CP_WAITN(0); else CP_WAITN(1);
        __syncthreads();
        const char* pA = sm + st * S_STAGE;
        const char* pB = pA + SA_BYTES;
        #pragma unroll
        for (int ks = 0; ks < 2; ks++) {
            const int kbyte = ks * 32 + qk * 2;
            uint32_t a[4][4], bb[4][2];
            #pragma unroll
            for (int mf = 0; mf < 4; mf++) {
                int r = wm * 64 + mf * 16 + qr;
                const char* base = pA + r * SA_STRIDE + kbyte;
                a[mf][0] = *(const uint32_t*)(base);
                a[mf][1] = *(const uint32_t*)(base + 8 * SA_STRIDE);
                a[mf][2] = *(const uint32_t*)(base + 16);
                a[mf][3] = *(const uint32_t*)(base + 8 * SA_STRIDE + 16);
            }
            #pragma unroll
            for (int nf = 0; nf < 4; nf++) {
                int n = wn * 32 + nf * 8 + qr;
                const char* base = pB + n * SA_STRIDE + kbyte;
                bb[nf][0] = *(const uint32_t*)(base);
                bb[nf][1] = *(const uint32_t*)(base + 16);
            }
            #pragma unroll
            for (int mf = 0; mf < 4; mf++)
                #pragma unroll
                for (int nf = 0; nf < 4; nf++)
                    MMA_BF16(acc[mf][nf], a[mf], bb[nf]);
        }
        __syncthreads();
        if (ch + 2 < 8) issue(ch + 2, st);
    }

    const int qc = (lane & 3) * 2;
    __nv_bfloat16* Eb = E + ((size_t)b * NN + i0) * NN + j0;
    #pragma unroll
    for (int mf = 0; mf < 4; mf++) {
        #pragma unroll
        for (int nf = 0; nf < 4; nf++) {
            int r = wm * 64 + mf * 16 + qr;
            int c = wn * 32 + nf * 8 + qc;
            *(__nv_bfloat162*)&Eb[(size_t)r * NN + c] =
                __floats2bfloat162_rn(__expf(acc[mf][nf][0]), __expf(acc[mf][nf][1]));
            *(__nv_bfloat162*)&Eb[(size_t)(r + 8) * NN + c] =
                __floats2bfloat162_rn(__expf(acc[mf][nf][2]), __expf(acc[mf][nf][3]));
        }
    }
}

// ===========================================================================
// rowsum: R[b,i] = sum_j E[b,i,j]   (f32 accumulate from stored bf16 E)
// ===========================================================================
__global__ void rowsum_kernel(const __nv_bfloat16* __restrict__ E,
                              float* __restrict__ R)
{
    const int i = blockIdx.x, b = blockIdx.y;
    const uint4* row = (const uint4*)(E + ((size_t)b * NN + i) * NN);
    const int tid = threadIdx.x;
    __shared__ float red[8];

    float s = 0.0f;
    #pragma unroll
    for (int u = 0; u < 2; u++) {
        uint4 v = row[tid + u * 256];
        uint32_t w[4] = {v.x, v.y, v.z, v.w};
        #pragma unroll
        for (int q = 0; q < 4; q++) {
            float2 f = __bfloat1622float2(*(const __nv_bfloat162*)&w[q]);
            s += f.x + f.y;
        }
    }
    #pragma unroll
    for (int off = 16; off > 0; off >>= 1)
        s += __shfl_xor_sync(0xFFFFFFFFu, s, off);
    if ((tid & 31) == 0) red[tid >> 5] = s;
    __syncthreads();
    if (tid == 0) {
        float t = 0.0f;
        #pragma unroll
        for (int w2 = 0; w2 < 8; w2++) t += red[w2];
        R[(size_t)b * NN + i] = t;
    }
}

// ===========================================================================
// vscale: Vb[b,c,i] = bf16( Vf[b,c,i] / R[b,i] )
// ===========================================================================
__global__ void vscale_kernel(const float* __restrict__ Vf,
                              const float* __restrict__ R,
                              __nv_bfloat16* __restrict__ Vb)
{
    size_t idx = ((size_t)blockIdx.x * 256 + threadIdx.x) * 4;
    int i = (int)(idx & (NN - 1));
    int b = (int)(idx >> 20);                 // CO*NN = 2^20
    float4 v = *(const float4*)&Vf[idx];
    float4 rr = *(const float4*)&R[(size_t)b * NN + i];
    *(uint2*)&Vb[idx] = pack4bf(v.x / rr.x, v.y / rr.y, v.z / rr.z, v.w / rr.w);
}

// ===========================================================================
// out_mma_d: out[b,c,j] = sum_i V'[b,c,i]*E[b,i,j] + xs2
// 256 threads, CTA 128(c) x 128(j). A direct b32; B ldmatrix.x2.trans.
// THIS ROUND: 3-stage cp.async pipeline (2 chunks in flight during compute).
// ===========================================================================
#define SBO_STRIDE 272                     // 128 bf16 (256B) + 16B pad
#define SBO_BYTES  (32 * SBO_STRIDE)       // 8704
#define O_STAGE    (SA_BYTES + SBO_BYTES)  // 18944
#define O_NSTAGE   3
#define O_SMEM     (O_NSTAGE * O_STAGE)    // 56832

__global__ void __launch_bounds__(256, 1)
out_mma_d(const __nv_bfloat16* __restrict__ V,
          const __nv_bfloat16* __restrict__ E,
          const float* __restrict__ xs2,
          float* __restrict__ out)
{
    extern __shared__ __align__(16) char sm[];
    const int tid = threadIdx.x, lane = tid & 31, wid = tid >> 5;
    const int b = blockIdx.z, c0 = blockIdx.y * 128, j0 = blockIdx.x * 128;
    const int wm = wid & 1, wn = wid >> 1;
    const int qr = lane >> 2;
    const int qk = (lane & 3) * 2;
    const int ln = lane & 15;

    const __nv_bfloat16* Ag = V + ((size_t)b * CO + c0) * NN;
    const __nv_bfloat16* Bg = E + (size_t)b * NN * NN + j0;
    const uint32_t sbase = smem_u32(sm);

    const int arow = tid >> 2, aseg = tid & 3;
    const int brow = tid >> 4, bseg = tid & 15;

    auto issue = [&](int ch, int st) {
        uint32_t sA = sbase + st * O_STAGE;
        uint32_t sB = sA + SA_BYTES;
        const __nv_bfloat16* a0 = Ag + ch * 32;
        const __nv_bfloat16* b0 = Bg + (size_t)(ch * 32) * NN;
        #pragma unroll
        for (int t = 0; t < 2; t++) {
            int ra = arow + t * 64;
            CP16(sA + (uint32_t)(ra * SA_STRIDE + aseg * 16),
                 a0 + (size_t)ra * NN + aseg * 8);
            int rb = brow + t * 16;
            CP16(sB + (uint32_t)(rb * SBO_STRIDE + bseg * 16),
                 b0 + (size_t)rb * NN + bseg * 8);
        }
        CP_COMMIT();
    };

    float acc[4][4][4] = {};
    issue(0, 0);
    issue(1, 1);
    issue(2, 2);

    const int NCH = NN / 32;   // 128
    int st = 0;
    #pragma unroll 1
    for (int ch = 0; ch < NCH; ch++) {
        // ensure group ch complete: allow at most min(2, NCH-1-ch) newer in flight
        if (ch < NCH - 2)      CP_WAITN(2);
        else if (ch == NCH - 2) CP_WAITN(1);
        else                    CP_WAITN(0);
        __syncthreads();
        const char* pA = sm + st * O_STAGE;
        const uint32_t sB32 = sbase + st * O_STAGE + SA_BYTES;
        #pragma unroll
        for (int ks = 0; ks < 2; ks++) {
            const int kbyteA = ks * 32 + qk * 2;
            const uint32_t brow_addr = sB32 + (uint32_t)((ks * 16 + ln) * SBO_STRIDE
                                                         + wn * 64);
            uint32_t a[4][4], bb[4][2];
            #pragma unroll
            for (int mf = 0; mf < 4; mf++) {
                int r = wm * 64 + mf * 16 + qr;
                const char* base = pA + r * SA_STRIDE + kbyteA;
                a[mf][0] = *(const uint32_t*)(base);
                a[mf][1] = *(const uint32_t*)(base + 8 * SA_STRIDE);
                a[mf][2] = *(const uint32_t*)(base + 16);
                a[mf][3] = *(const uint32_t*)(base + 8 * SA_STRIDE + 16);
            }
            #pragma unroll
            for (int nf = 0; nf < 4; nf++)
                LDSM2T(bb[nf][0], bb[nf][1], brow_addr + nf * 16);
            #pragma unroll
            for (int mf = 0; mf < 4; mf++)
                #pragma unroll
                for (int nf = 0; nf < 4; nf++)
                    MMA_BF16(acc[mf][nf], a[mf], bb[nf]);
        }
        __syncthreads();
        if (ch + 3 < NCH) issue(ch + 3, st);   // refill the stage just consumed
        st = (st == O_NSTAGE - 1) ? 0 : st + 1;
    }

    const int qc = (lane & 3) * 2;
    const float* Xb = xs2 + ((size_t)b * CO + c0) * NN + j0;
    float* Ob = out + ((size_t)b * CO + c0) * NN + j0;
    #pragma unroll
    for (int mf = 0; mf < 4; mf++) {
        #pragma unroll
        for (int nf = 0; nf < 4; nf++) {
            int r = wm * 64 + mf * 16 + qr;
            int c = wn * 32 + nf * 8 + qc;
            float2 x0 = *(const float2*)&Xb[(size_t)r * NN + c];
            float2 x1 = *(const float2*)&Xb[(size_t)(r + 8) * NN + c];
            *(float2*)&Ob[(size_t)r * NN + c] =
                make_float2(acc[mf][nf][0] + x0.x, acc[mf][nf][1] + x0.y);
            *(float2*)&Ob[(size_t)(r + 8) * NN + c] =
                make_float2(acc[mf][nf][2] + x1.x, acc[mf][nf][3] + x1.y);
        }
    }
}

// ===========================================================================
// Projection (R1-proven, f32 out)
// ===========================================================================
template <int CIN>
__global__ void proj_kernel(const float* __restrict__ X,
                            const float* __restrict__ W,
                            const float* __restrict__ bias,
                            float* __restrict__ Y)
{
    const int b  = blockIdx.z;
    const int j0 = blockIdx.x * 64;
    const int m0 = blockIdx.y * 64;

    __shared__ float As[16][68];
    __shared__ float Bs[16][68];

    const int tid = threadIdx.x;
    const int tx = tid & 15;
    const int ty = tid >> 4;

    const float* Xb = X + (size_t)b * CIN * NN;
    float acc[4][4] = {};

    for (int k0 = 0; k0 < CIN; k0 += 16) {
        {
            int m  = tid >> 2;
            int kq = (tid & 3) * 4;
            float4 w4 = *(const float4*)&W[(size_t)(m0 + m) * CIN + k0 + kq];
            As[kq + 0][m] = w4.x; As[kq + 1][m] = w4.y;
            As[kq + 2][m] = w4.z; As[kq + 3][m] = w4.w;
        }
        {
            int k  = tid >> 4;
            int jq = (tid & 15) * 4;
            *(float4*)&Bs[k][jq] = *(const float4*)&Xb[(size_t)(k0 + k) * NN + j0 + jq];
        }
        __syncthreads();
        #pragma unroll
        for (int k = 0; k < 16; k++) {
            float4 a4 = *(const float4*)&As[k][ty * 4];
            float4 b4 = *(const float4*)&Bs[k][tx * 4];
            float a[4] = {a4.x, a4.y, a4.z, a4.w};
            float bv[4] = {b4.x, b4.y, b4.z, b4.w};
            #pragma unroll
            for (int i = 0; i < 4; i++)
                #pragma unroll
                for (int j = 0; j < 4; j++)
                    acc[i][j] += a[i] * bv[j];
        }
        __syncthreads();
    }

    float* Yb = Y + (size_t)b * CO * NN;
    #pragma unroll
    for (int i = 0; i < 4; i++) {
        int m = m0 + ty * 4 + i;
        float bs = bias[m];
        *(float4*)&Yb[(size_t)m * NN + j0 + tx * 4] =
            make_float4(acc[i][0] + bs, acc[i][1] + bs,
                        acc[i][2] + bs, acc[i][3] + bs);
    }
}

// ===========================================================================
// Tiled transpose + scale + bf16: Yt[b][n][c] = bf16(X[b][c][n] * scale)
// ===========================================================================
__global__ void transpose_scale_bf16(const float* __restrict__ X,
                                     __nv_bfloat16* __restrict__ Yt,
                                     float scale)
{
    __shared__ float t[32][33];
    const int b  = blockIdx.z;
    const int n0 = blockIdx.x * 32;
    const int c0 = blockIdx.y * 32;
    const int tx = threadIdx.x, ty = threadIdx.y;

    const float* Xb = X + ((size_t)b * CO + c0) * NN + n0;
    #pragma unroll
    for (int k = 0; k < 4; k++) {
        int r = ty + k * 8;
        t[r][tx] = Xb[(size_t)r * NN + tx];
    }
    __syncthreads();

    __nv_bfloat16* Yb = Yt + ((size_t)b * NN + n0) * CO + c0;
    #pragma unroll
    for (int k = 0; k < 4; k++) {
        int r = ty + k * 8;
        Yb[(size_t)r * CO + tx] = __float2bfloat16(t[tx][r] * scale);
    }
}

// ===========================================================================
extern "C" void kernel_launch(void* const* d_in, const int* in_sizes, int n_in,
                              void* d_out, int out_size)
{
    const float* x_s2  = (const float*)d_in[0];
    const float* x_dem = (const float*)d_in[1];
    const float* Wq    = (const float*)d_in[2];
    const float* bq    = (const float*)d_in[3];
    const float* Wk    = (const float*)d_in[4];
    const float* bk    = (const float*)d_in[5];
    const float* Wv    = (const float*)d_in[6];
    const float* bv    = (const float*)d_in[7];
    float* out = (float*)d_out;

    float *Qf, *Kf, *Vf, *Rp;
    __nv_bfloat16 *Qt, *Kt, *Vb, *Ep;
    cudaGetSymbolAddress((void**)&Qf, g_Qf);
    cudaGetSymbolAddress((void**)&Kf, g_Kf);
    cudaGetSymbolAddress((void**)&Vf, g_Vf);
    cudaGetSymbolAddress((void**)&Qt, g_Qt);
    cudaGetSymbolAddress((void**)&Kt, g_Kt);
    cudaGetSymbolAddress((void**)&Vb, g_Vb);
    cudaGetSymbolAddress((void**)&Ep, g_E);
    cudaGetSymbolAddress((void**)&Rp, g_R);

    cudaFuncSetAttribute(out_mma_d, cudaFuncAttributeMaxDynamicSharedMemorySize, O_SMEM);

    dim3 blk(256);
    dim3 grid_proj(NN / 64, CO / 64, BB);
    proj_kernel<CS><<<grid_proj, blk>>>(x_s2,  Wq, bq, Qf);
    proj_kernel<CD><<<grid_proj, blk>>>(x_dem, Wk, bk, Kf);
    proj_kernel<CD><<<grid_proj, blk>>>(x_dem, Wv, bv, Vf);

    dim3 grid_tr(NN / 32, CO / 32, BB);
    dim3 blk_tr(32, 8);
    transpose_scale_bf16<<<grid_tr, blk_tr>>>(Qf, Qt, SCALE);
    transpose_scale_bf16<<<grid_tr, blk_tr>>>(Kf, Kt, 1.0f);

    s_mma_d<<<dim3(NN / 128, NN / 128, BB), blk>>>(Kt, Qt, Ep);

    rowsum_kernel<<<dim3(NN, BB), blk>>>(Ep, Rp);

    vscale_kernel<<<(unsigned)((size_t)BB * CO * NN / 1024), 256>>>(Vf, Rp, Vb);

    out_mma_d<<<dim3(NN / 128, CO / 128, BB), blk, O_SMEM>>>(Vb, Ep, x_s2, out);
}

// round 14
// speedup vs baseline: 1.1371x; 1.0351x over previous
#include <cuda_runtime.h>
#include <cuda_bf16.h>
#include <cstdint>

// CrossAttentionFusion: B=4, S2_CH=256, DEM_CH=64, OUT_CH=256, H=W=64, N=4096
#define BB 4
#define CS 256
#define CD 64
#define CO 256
#define NN 4096
#define SCALE 0.0625f

// Scratch (device globals: allocation-free rule)
__device__ __nv_bfloat16 g_Qb[(size_t)BB * CO * NN];   // proj Q bf16 [b][o][n]
__device__ __nv_bfloat16 g_Kb[(size_t)BB * CO * NN];   // proj K bf16 [b][o][n]
__device__ __nv_bfloat16 g_Vr[(size_t)BB * CO * NN];   // proj V bf16 [b][c][i] (unscaled)
__device__ __nv_bfloat16 g_Qt[(size_t)BB * NN * CO];   // Q^T bf16 [b][j][c] (scale folded)
__device__ __nv_bfloat16 g_Kt[(size_t)BB * NN * CO];   // K^T bf16 [b][i][c]
__device__ __nv_bfloat16 g_Vb[(size_t)BB * CO * NN];   // V' = V/R bf16 [b][c][i]
__device__ __nv_bfloat16 g_E [(size_t)BB * NN * NN];   // exp(logits) bf16 [b][i][j]
__device__ float         g_R [(size_t)BB * NN];        // row sums of E

// ===========================================================================
// helpers
// ===========================================================================
__device__ __forceinline__ uint32_t smem_u32(const void* p) {
    uint32_t a;
    asm("{ .reg .u64 t; cvta.to.shared.u64 t, %1; cvt.u32.u64 %0, t; }"
        : "=r"(a) : "l"(p));
    return a;
}

#define CP16(dst, src) \
    asm volatile("cp.async.cg.shared.global [%0], [%1], 16;" \
                 :: "r"(dst), "l"(src))
#define CP_COMMIT() asm volatile("cp.async.commit_group;" ::: "memory")
#define CP_WAITN(n) asm volatile("cp.async.wait_group %0;" :: "n"(n) : "memory")

#define LDSM2T(r0, r1, addr) \
    asm volatile("ldmatrix.sync.aligned.m8n8.x2.trans.shared.b16 {%0,%1}, [%2];" \
                 : "=r"(r0), "=r"(r1) : "r"(addr))

#define MMA_BF16(d, av, bv) \
    asm volatile("mma.sync.aligned.m16n8k16.row.col.f32.bf16.bf16.f32 " \
                 "{%0,%1,%2,%3}, {%4,%5,%6,%7}, {%8,%9}, {%0,%1,%2,%3};" \
                 : "+f"((d)[0]), "+f"((d)[1]), "+f"((d)[2]), "+f"((d)[3]) \
                 : "r"((av)[0]), "r"((av)[1]), "r"((av)[2]), "r"((av)[3]), \
                   "r"((bv)[0]), "r"((bv)[1]))

__device__ __forceinline__ uint2 pack4bf(float a, float b, float c, float d) {
    __nv_bfloat162 lo = __floats2bfloat162_rn(a, b);
    __nv_bfloat162 hi = __floats2bfloat162_rn(c, d);
    uint2 r;
    r.x = *(uint32_t*)&lo;
    r.y = *(uint32_t*)&hi;
    return r;
}

// ===========================================================================
// s_mma_d: E[b,i,j] = exp( sum_c Kt[b,i,c] * Qt[b,j,c] )   (scale in Qt)
// CTA 128(i) x 128(j), 8 warps (warp tile 64x32), k-chunks of 32, 2-stage.
// (R12-proven: direct b32 fragment loads for A and B.)
// ===========================================================================
#define SA_STRIDE 80                       // 32 bf16 (64B) + 16B pad
#define SA_BYTES  (128 * SA_STRIDE)        // 10240
#define S_STAGE   (2 * SA_BYTES)

__global__ void __launch_bounds__(256, 1)
s_mma_d(const __nv_bfloat16* __restrict__ Kt,
        const __nv_bfloat16* __restrict__ Qt,
        __nv_bfloat16* __restrict__ E)
{
    __shared__ __align__(16) char sm[2 * S_STAGE];   // 40 KB
    const int tid = threadIdx.x, lane = tid & 31, wid = tid >> 5;
    const int b = blockIdx.z, i0 = blockIdx.y * 128, j0 = blockIdx.x * 128;
    const int wm = wid & 1, wn = wid >> 1;
    const int qr = lane >> 2;
    const int qk = (lane & 3) * 2;

    const __nv_bfloat16* Ag = Kt + ((size_t)b * NN + i0) * CS;
    const __nv_bfloat16* Bg = Qt + ((size_t)b * NN + j0) * CS;
    const uint32_t sbase = smem_u32(sm);

    const int crow = tid >> 2, cseg = tid & 3;

    auto issue = [&](int ch, int st) {
        uint32_t sA = sbase + st * S_STAGE;
        uint32_t sB = sA + SA_BYTES;
        const __nv_bfloat16* a0 = Ag + ch * 32;
        const __nv_bfloat16* b0 = Bg + ch * 32;
        #pragma unroll
        for (int t = 0; t < 2; t++) {
            int row = crow + t * 64;
            uint32_t off = (uint32_t)(row * SA_STRIDE + cseg * 16);
            CP16(sA + off, a0 + (size_t)row * CS + cseg * 8);
            CP16(sB + off, b0 + (size_t)row * CS + cseg * 8);
        }
        CP_COMMIT();
    };

    float acc[4][4][4] = {};
    issue(0, 0);
    issue(1, 1);

    #pragma unroll 1
    for (int ch = 0; ch < 8; ch++) {
        const int st = ch & 1;
        if (ch == 7) CP_WAITN(0); else CP_WAITN(1);
        __syncthreads();
        const char* pA = sm + st * S_STAGE;
        const char* pB = pA + SA_BYTES;
        #pragma unroll
        for (int ks = 0; ks < 2; ks++) {
            const int kbyte = ks * 32 + qk * 2;
            uint32_t a[4][4], bb[4][2];
            #pragma unroll
            for (int mf = 0; mf < 4; mf++) {
                int r = wm * 64 + mf * 16 + qr;
                const char* base = pA + r * SA_STRIDE + kbyte;
                a[mf][0] = *(const uint32_t*)(base);
                a[mf][1] = *(const uint32_t*)(base + 8 * SA_STRIDE);
                a[mf][2] = *(const uint32_t*)(base + 16);
                a[mf][3] = *(const uint32_t*)(base + 8 * SA_STRIDE + 16);
            }
            #pragma unroll
            for (int nf = 0; nf < 4; nf++) {
                int n = wn * 32 + nf * 8 + qr;
                const char* base = pB + n * SA_STRIDE + kbyte;
                bb[nf][0] = *(const uint32_t*)(base);
                bb[nf][1] = *(const uint32_t*)(base + 16);
            }
            #pragma unroll
            for (int mf = 0; mf < 4; mf++)
                #pragma unroll
                for (int nf = 0; nf < 4; nf++)
                    MMA_BF16(acc[mf][nf], a[mf], bb[nf]);
        }
        __syncthreads();
        if (ch + 2 < 8) issue(ch + 2, st);
    }

    const int qc = (lane & 3) * 2;
    __nv_bfloat16* Eb = E + ((size_t)b * NN + i0) * NN + j0;
    #pragma unroll
    for (int mf = 0; mf < 4; mf++) {
        #pragma unroll
        for (int nf = 0; nf < 4; nf++) {
            int r = wm * 64 + mf * 16 + qr;
            int c = wn * 32 + nf * 8 + qc;
            *(__nv_bfloat162*)&Eb[(size_t)r * NN + c] =
                __floats2bfloat162_rn(__expf(acc[mf][nf][0]), __expf(acc[mf][nf][1]));
            *(__nv_bfloat162*)&Eb[(size_t)(r + 8) * NN + c] =
                __floats2bfloat162_rn(__expf(acc[mf][nf][2]), __expf(acc[mf][nf][3]));
        }
    }
}

// ===========================================================================
// rowsum: R[b,i] = sum_j E[b,i,j]   (f32 accumulate from stored bf16 E)
// ===========================================================================
__global__ void rowsum_kernel(const __nv_bfloat16* __restrict__ E,
                              float* __restrict__ R)
{
    const int i = blockIdx.x, b = blockIdx.y;
    const uint4* row = (const uint4*)(E + ((size_t)b * NN + i) * NN);
    const int tid = threadIdx.x;
    __shared__ float red[8];

    float s = 0.0f;
    #pragma unroll
    for (int u = 0; u < 2; u++) {
        uint4 v = row[tid + u * 256];
        uint32_t w[4] = {v.x, v.y, v.z, v.w};
        #pragma unroll
        for (int q = 0; q < 4; q++) {
            float2 f = __bfloat1622float2(*(const __nv_bfloat162*)&w[q]);
            s += f.x + f.y;
        }
    }
    #pragma unroll
    for (int off = 16; off > 0; off >>= 1)
        s += __shfl_xor_sync(0xFFFFFFFFu, s, off);
    if ((tid & 31) == 0) red[tid >> 5] = s;
    __syncthreads();
    if (tid == 0) {
        float t = 0.0f;
        #pragma unroll
        for (int w2 = 0; w2 < 8; w2++) t += red[w2];
        R[(size_t)b * NN + i] = t;
    }
}

// ===========================================================================
// vscale: Vb[b,c,i] = bf16( f32(Vr[b,c,i]) / R[b,i] )    (bf16 in, bf16 out)
// 8 elements per thread.
// ===========================================================================
__global__ void vscale_kernel(const __nv_bfloat16* __restrict__ Vr,
                              const float* __restrict__ R,
                              __nv_bfloat16* __restrict__ Vb)
{
    size_t idx = ((size_t)blockIdx.x * 256 + threadIdx.x) * 8;
    int i = (int)(idx & (NN - 1));
    int b = (int)(idx >> 20);                 // CO*NN = 2^20
    uint4 v = *(const uint4*)&Vr[idx];
    float4 r0 = *(const float4*)&R[(size_t)b * NN + i];
    float4 r1 = *(const float4*)&R[(size_t)b * NN + i + 4];
    float2 f0 = __bfloat1622float2(*(const __nv_bfloat162*)&v.x);
    float2 f1 = __bfloat1622float2(*(const __nv_bfloat162*)&v.y);
    float2 f2 = __bfloat1622float2(*(const __nv_bfloat162*)&v.z);
    float2 f3 = __bfloat1622float2(*(const __nv_bfloat162*)&v.w);
    uint2 o0 = pack4bf(f0.x / r0.x, f0.y / r0.y, f1.x / r0.z, f1.y / r0.w);
    uint2 o1 = pack4bf(f2.x / r1.x, f2.y / r1.y, f3.x / r1.z, f3.y / r1.w);
    uint4 o = make_uint4(o0.x, o0.y, o1.x, o1.y);
    *(uint4*)&Vb[idx] = o;
}

// ===========================================================================
// out_mma_d: out[b,c,j] = sum_i V'[b,c,i]*E[b,i,j] + xs2
// 256 threads, CTA 128(c) x 128(j). A direct b32; B ldmatrix.x2.trans.
// 3-stage cp.async pipeline (R12-proven).
// ===========================================================================
#define SBO_STRIDE 272                     // 128 bf16 (256B) + 16B pad
#define SBO_BYTES  (32 * SBO_STRIDE)       // 8704
#define O_STAGE    (SA_BYTES + SBO_BYTES)  // 18944
#define O_NSTAGE   3
#define O_SMEM     (O_NSTAGE * O_STAGE)    // 56832

__global__ void __launch_bounds__(256, 1)
out_mma_d(const __nv_bfloat16* __restrict__ V,
          const __nv_bfloat16* __restrict__ E,
          const float* __restrict__ xs2,
          float* __restrict__ out)
{
    extern __shared__ __align__(16) char sm[];
    const int tid = threadIdx.x, lane = tid & 31, wid = tid >> 5;
    const int b = blockIdx.z, c0 = blockIdx.y * 128, j0 = blockIdx.x * 128;
    const int wm = wid & 1, wn = wid >> 1;
    const int qr = lane >> 2;
    const int qk = (lane & 3) * 2;
    const int ln = lane & 15;

    const __nv_bfloat16* Ag = V + ((size_t)b * CO + c0) * NN;
    const __nv_bfloat16* Bg = E + (size_t)b * NN * NN + j0;
    const uint32_t sbase = smem_u32(sm);

    const int arow = tid >> 2, aseg = tid & 3;
    const int brow = tid >> 4, bseg = tid & 15;

    auto issue = [&](int ch, int st) {
        uint32_t sA = sbase + st * O_STAGE;
        uint32_t sB = sA + SA_BYTES;
        const __nv_bfloat16* a0 = Ag + ch * 32;
        const __nv_bfloat16* b0 = Bg + (size_t)(ch * 32) * NN;
        #pragma unroll
        for (int t = 0; t < 2; t++) {
            int ra = arow + t * 64;
            CP16(sA + (uint32_t)(ra * SA_STRIDE + aseg * 16),
                 a0 + (size_t)ra * NN + aseg * 8);
            int rb = brow + t * 16;
            CP16(sB + (uint32_t)(rb * SBO_STRIDE + bseg * 16),
                 b0 + (size_t)rb * NN + bseg * 8);
        }
        CP_COMMIT();
    };

    float acc[4][4][4] = {};
    issue(0, 0);
    issue(1, 1);
    issue(2, 2);

    const int NCH = NN / 32;   // 128
    int st = 0;
    #pragma unroll 1
    for (int ch = 0; ch < NCH; ch++) {
        if (ch < NCH - 2)       CP_WAITN(2);
        else if (ch == NCH - 2) CP_WAITN(1);
        else                    CP_WAITN(0);
        __syncthreads();
        const char* pA = sm + st * O_STAGE;
        const uint32_t sB32 = sbase + st * O_STAGE + SA_BYTES;
        #pragma unroll
        for (int ks = 0; ks < 2; ks++) {
            const int kbyteA = ks * 32 + qk * 2;
            const uint32_t brow_addr = sB32 + (uint32_t)((ks * 16 + ln) * SBO_STRIDE
                                                         + wn * 64);
            uint32_t a[4][4], bb[4][2];
            #pragma unroll
            for (int mf = 0; mf < 4; mf++) {
                int r = wm * 64 + mf * 16 + qr;
                const char* base = pA + r * SA_STRIDE + kbyteA;
                a[mf][0] = *(const uint32_t*)(base);
                a[mf][1] = *(const uint32_t*)(base + 8 * SA_STRIDE);
                a[mf][2] = *(const uint32_t*)(base + 16);
                a[mf][3] = *(const uint32_t*)(base + 8 * SA_STRIDE + 16);
            }
            #pragma unroll
            for (int nf = 0; nf < 4; nf++)
                LDSM2T(bb[nf][0], bb[nf][1], brow_addr + nf * 16);
            #pragma unroll
            for (int mf = 0; mf < 4; mf++)
                #pragma unroll
                for (int nf = 0; nf < 4; nf++)
                    MMA_BF16(acc[mf][nf], a[mf], bb[nf]);
        }
        __syncthreads();
        if (ch + 3 < NCH) issue(ch + 3, st);   // refill the stage just consumed
        st = (st == O_NSTAGE - 1) ? 0 : st + 1;
    }

    const int qc = (lane & 3) * 2;
    const float* Xb = xs2 + ((size_t)b * CO + c0) * NN + j0;
    float* Ob = out + ((size_t)b * CO + c0) * NN + j0;
    #pragma unroll
    for (int mf = 0; mf < 4; mf++) {
        #pragma unroll
        for (int nf = 0; nf < 4; nf++) {
            int r = wm * 64 + mf * 16 + qr;
            int c = wn * 32 + nf * 8 + qc;
            float2 x0 = *(const float2*)&Xb[(size_t)r * NN + c];
            float2 x1 = *(const float2*)&Xb[(size_t)(r + 8) * NN + c];
            *(float2*)&Ob[(size_t)r * NN + c] =
                make_float2(acc[mf][nf][0] + x0.x, acc[mf][nf][1] + x0.y);
            *(float2*)&Ob[(size_t)(r + 8) * NN + c] =
                make_float2(acc[mf][nf][2] + x1.x, acc[mf][nf][3] + x1.y);
        }
    }
}

// ===========================================================================
// Projection (R1-proven core, bf16 epilogue):
// Y[b,o,j] = bf16( sum_c W[o,c] X[b,c,j] + bias[o] )
// ===========================================================================
template <int CIN>
__global__ void proj_kernel(const float* __restrict__ X,
                            const float* __restrict__ W,
                            const float* __restrict__ bias,
                            __nv_bfloat16* __restrict__ Y)
{
    const int b  = blockIdx.z;
    const int j0 = blockIdx.x * 64;
    const int m0 = blockIdx.y * 64;

    __shared__ float As[16][68];
    __shared__ float Bs[16][68];

    const int tid = threadIdx.x;
    const int tx = tid & 15;
    const int ty = tid >> 4;

    const float* Xb = X + (size_t)b * CIN * NN;
    float acc[4][4] = {};

    for (int k0 = 0; k0 < CIN; k0 += 16) {
        {
            int m  = tid >> 2;
            int kq = (tid & 3) * 4;
            float4 w4 = *(const float4*)&W[(size_t)(m0 + m) * CIN + k0 + kq];
            As[kq + 0][m] = w4.x; As[kq + 1][m] = w4.y;
            As[kq + 2][m] = w4.z; As[kq + 3][m] = w4.w;
        }
        {
            int k  = tid >> 4;
            int jq = (tid & 15) * 4;
            *(float4*)&Bs[k][jq] = *(const float4*)&Xb[(size_t)(k0 + k) * NN + j0 + jq];
        }
        __syncthreads();
        #pragma unroll
        for (int k = 0; k < 16; k++) {
            float4 a4 = *(const float4*)&As[k][ty * 4];
            float4 b4 = *(const float4*)&Bs[k][tx * 4];
            float a[4] = {a4.x, a4.y, a4.z, a4.w};
            float bv[4] = {b4.x, b4.y, b4.z, b4.w};
            #pragma unroll
            for (int i = 0; i < 4; i++)
                #pragma unroll
                for (int j = 0; j < 4; j++)
                    acc[i][j] += a[i] * bv[j];
        }
        __syncthreads();
    }

    __nv_bfloat16* Yb = Y + (size_t)b * CO * NN;
    #pragma unroll
    for (int i = 0; i < 4; i++) {
        int m = m0 + ty * 4 + i;
        float bs = bias[m];
        uint2 r = pack4bf(acc[i][0] + bs, acc[i][1] + bs,
                          acc[i][2] + bs, acc[i][3] + bs);
        *(uint2*)&Yb[(size_t)m * NN + j0 + tx * 4] = r;
    }
}

// ===========================================================================
// Tiled transpose + scale, bf16 in / bf16 out: Yt[b][n][c] = X[b][c][n]*scale
// ===========================================================================
__global__ void transpose_scale_bf16(const __nv_bfloat16* __restrict__ X,
                                     __nv_bfloat16* __restrict__ Yt,
                                     float scale)
{
    __shared__ float t[32][33];
    const int b  = blockIdx.z;
    const int n0 = blockIdx.x * 32;
    const int c0 = blockIdx.y * 32;
    const int tx = threadIdx.x, ty = threadIdx.y;

    const __nv_bfloat16* Xb = X + ((size_t)b * CO + c0) * NN + n0;
    #pragma unroll
    for (int k = 0; k < 4; k++) {
        int r = ty + k * 8;
        t[r][tx] = __bfloat162float(Xb[(size_t)r * NN + tx]);
    }
    __syncthreads();

    __nv_bfloat16* Yb = Yt + ((size_t)b * NN + n0) * CO + c0;
    #pragma unroll
    for (int k = 0; k < 4; k++) {
        int r = ty + k * 8;
        Yb[(size_t)r * CO + tx] = __float2bfloat16(t[tx][r] * scale);
    }
}

// ===========================================================================
extern "C" void kernel_launch(void* const* d_in, const int* in_sizes, int n_in,
                              void* d_out, int out_size)
{
    const float* x_s2  = (const float*)d_in[0];
    const float* x_dem = (const float*)d_in[1];
    const float* Wq    = (const float*)d_in[2];
    const float* bq    = (const float*)d_in[3];
    const float* Wk    = (const float*)d_in[4];
    const float* bk    = (const float*)d_in[5];
    const float* Wv    = (const float*)d_in[6];
    const float* bv    = (const float*)d_in[7];
    float* out = (float*)d_out;

    float* Rp;
    __nv_bfloat16 *Qb, *Kb, *Vr, *Qt, *Kt, *Vb, *Ep;
    cudaGetSymbolAddress((void**)&Qb, g_Qb);
    cudaGetSymbolAddress((void**)&Kb, g_Kb);
    cudaGetSymbolAddress((void**)&Vr, g_Vr);
    cudaGetSymbolAddress((void**)&Qt, g_Qt);
    cudaGetSymbolAddress((void**)&Kt, g_Kt);
    cudaGetSymbolAddress((void**)&Vb, g_Vb);
    cudaGetSymbolAddress((void**)&Ep, g_E);
    cudaGetSymbolAddress((void**)&Rp, g_R);

    cudaFuncSetAttribute(out_mma_d, cudaFuncAttributeMaxDynamicSharedMemorySize, O_SMEM);

    dim3 blk(256);
    dim3 grid_proj(NN / 64, CO / 64, BB);
    proj_kernel<CS><<<grid_proj, blk>>>(x_s2,  Wq, bq, Qb);
    proj_kernel<CD><<<grid_proj, blk>>>(x_dem, Wk, bk, Kb);
    proj_kernel<CD><<<grid_proj, blk>>>(x_dem, Wv, bv, Vr);

    dim3 grid_tr(NN / 32, CO / 32, BB);
    dim3 blk_tr(32, 8);
    transpose_scale_bf16<<<grid_tr, blk_tr>>>(Qb, Qt, SCALE);
    transpose_scale_bf16<<<grid_tr, blk_tr>>>(Kb, Kt, 1.0f);

    s_mma_d<<<dim3(NN / 128, NN / 128, BB), blk>>>(Kt, Qt, Ep);

    rowsum_kernel<<<dim3(NN, BB), blk>>>(Ep, Rp);

    vscale_kernel<<<(unsigned)((size_t)BB * CO * NN / 2048), 256>>>(Vr, Rp, Vb);

    out_mma_d<<<dim3(NN / 128, CO / 128, BB), blk, O_SMEM>>>(Vb, Ep, x_s2, out);
}

// round 15
// speedup vs baseline: 1.1747x; 1.0331x over previous
#include <cuda_runtime.h>
#include <cuda_bf16.h>
#include <cstdint>

// CrossAttentionFusion: B=4, S2_CH=256, DEM_CH=64, OUT_CH=256, H=W=64, N=4096
#define BB 4
#define CS 256
#define CD 64
#define CO 256
#define NN 4096
#define SCALE 0.0625f

// Scratch (device globals: allocation-free rule)
__device__ __nv_bfloat16 g_Qb[(size_t)BB * CO * NN];   // proj Q bf16 [b][o][n]
__device__ __nv_bfloat16 g_Kb[(size_t)BB * CO * NN];   // proj K bf16 [b][o][n]
__device__ __nv_bfloat16 g_Vr[(size_t)BB * CO * NN];   // proj V bf16 [b][c][i] (unscaled)
__device__ __nv_bfloat16 g_Qt[(size_t)BB * NN * CO];   // Q^T bf16 [b][j][c] (scale folded)
__device__ __nv_bfloat16 g_Kt[(size_t)BB * NN * CO];   // K^T bf16 [b][i][c]
__device__ __nv_bfloat16 g_Vb[(size_t)BB * CO * NN];   // V' = V/R bf16 [b][c][i]
__device__ __nv_bfloat16 g_E [(size_t)BB * NN * NN];   // exp(logits) bf16 [b][i][j]
__device__ float         g_R [(size_t)BB * NN];        // row sums of E

// ===========================================================================
// helpers
// ===========================================================================
__device__ __forceinline__ uint32_t smem_u32(const void* p) {
    uint32_t a;
    asm("{ .reg .u64 t; cvta.to.shared.u64 t, %1; cvt.u32.u64 %0, t; }"
        : "=r"(a) : "l"(p));
    return a;
}

#define CP16(dst, src) \
    asm volatile("cp.async.cg.shared.global [%0], [%1], 16;" \
                 :: "r"(dst), "l"(src))
#define CP_COMMIT() asm volatile("cp.async.commit_group;" ::: "memory")
#define CP_WAITN(n) asm volatile("cp.async.wait_group %0;" :: "n"(n) : "memory")

#define LDSM2T(r0, r1, addr) \
    asm volatile("ldmatrix.sync.aligned.m8n8.x2.trans.shared.b16 {%0,%1}, [%2];" \
                 : "=r"(r0), "=r"(r1) : "r"(addr))

#define MMA_BF16(d, av, bv) \
    asm volatile("mma.sync.aligned.m16n8k16.row.col.f32.bf16.bf16.f32 " \
                 "{%0,%1,%2,%3}, {%4,%5,%6,%7}, {%8,%9}, {%0,%1,%2,%3};" \
                 : "+f"((d)[0]), "+f"((d)[1]), "+f"((d)[2]), "+f"((d)[3]) \
                 : "r"((av)[0]), "r"((av)[1]), "r"((av)[2]), "r"((av)[3]), \
                   "r"((bv)[0]), "r"((bv)[1]))

__device__ __forceinline__ uint2 pack4bf(float a, float b, float c, float d) {
    __nv_bfloat162 lo = __floats2bfloat162_rn(a, b);
    __nv_bfloat162 hi = __floats2bfloat162_rn(c, d);
    uint2 r;
    r.x = *(uint32_t*)&lo;
    r.y = *(uint32_t*)&hi;
    return r;
}

// ===========================================================================
// s_mma_d: E[b,i,j] = exp( sum_c Kt[b,i,c] * Qt[b,j,c] )   (scale in Qt)
// CTA 128(i) x 128(j), 8 warps (warp tile 64x32), k-chunks of 32, 2-stage.
// ===========================================================================
#define SA_STRIDE 80                       // 32 bf16 (64B) + 16B pad
#define SA_BYTES  (128 * SA_STRIDE)        // 10240
#define S_STAGE   (2 * SA_BYTES)

__global__ void __launch_bounds__(256, 1)
s_mma_d(const __nv_bfloat16* __restrict__ Kt,
        const __nv_bfloat16* __restrict__ Qt,
        __nv_bfloat16* __restrict__ E)
{
    __shared__ __align__(16) char sm[2 * S_STAGE];   // 40 KB
    const int tid = threadIdx.x, lane = tid & 31, wid = tid >> 5;
    const int b = blockIdx.z, i0 = blockIdx.y * 128, j0 = blockIdx.x * 128;
    const int wm = wid & 1, wn = wid >> 1;
    const int qr = lane >> 2;
    const int qk = (lane & 3) * 2;

    const __nv_bfloat16* Ag = Kt + ((size_t)b * NN + i0) * CS;
    const __nv_bfloat16* Bg = Qt + ((size_t)b * NN + j0) * CS;
    const uint32_t sbase = smem_u32(sm);

    const int crow = tid >> 2, cseg = tid & 3;

    auto issue = [&](int ch, int st) {
        uint32_t sA = sbase + st * S_STAGE;
        uint32_t sB = sA + SA_BYTES;
        const __nv_bfloat16* a0 = Ag + ch * 32;
        const __nv_bfloat16* b0 = Bg + ch * 32;
        #pragma unroll
        for (int t = 0; t < 2; t++) {
            int row = crow + t * 64;
            uint32_t off = (uint32_t)(row * SA_STRIDE + cseg * 16);
            CP16(sA + off, a0 + (size_t)row * CS + cseg * 8);
            CP16(sB + off, b0 + (size_t)row * CS + cseg * 8);
        }
        CP_COMMIT();
    };

    float acc[4][4][4] = {};
    issue(0, 0);
    issue(1, 1);

    #pragma unroll 1
    for (int ch = 0; ch < 8; ch++) {
        const int st = ch & 1;
        if (ch == 7) CP_WAITN(0); else CP_WAITN(1);
        __syncthreads();
        const char* pA = sm + st * S_STAGE;
        const char* pB = pA + SA_BYTES;
        #pragma unroll
        for (int ks = 0; ks < 2; ks++) {
            const int kbyte = ks * 32 + qk * 2;
            uint32_t a[4][4], bb[4][2];
            #pragma unroll
            for (int mf = 0; mf < 4; mf++) {
                int r = wm * 64 + mf * 16 + qr;
                const char* base = pA + r * SA_STRIDE + kbyte;
                a[mf][0] = *(const uint32_t*)(base);
                a[mf][1] = *(const uint32_t*)(base + 8 * SA_STRIDE);
                a[mf][2] = *(const uint32_t*)(base + 16);
                a[mf][3] = *(const uint32_t*)(base + 8 * SA_STRIDE + 16);
            }
            #pragma unroll
            for (int nf = 0; nf < 4; nf++) {
                int n = wn * 32 + nf * 8 + qr;
                const char* base = pB + n * SA_STRIDE + kbyte;
                bb[nf][0] = *(const uint32_t*)(base);
                bb[nf][1] = *(const uint32_t*)(base + 16);
            }
            #pragma unroll
            for (int mf = 0; mf < 4; mf++)
                #pragma unroll
                for (int nf = 0; nf < 4; nf++)
                    MMA_BF16(acc[mf][nf], a[mf], bb[nf]);
        }
        __syncthreads();
        if (ch + 2 < 8) issue(ch + 2, st);
    }

    const int qc = (lane & 3) * 2;
    __nv_bfloat16* Eb = E + ((size_t)b * NN + i0) * NN + j0;
    #pragma unroll
    for (int mf = 0; mf < 4; mf++) {
        #pragma unroll
        for (int nf = 0; nf < 4; nf++) {
            int r = wm * 64 + mf * 16 + qr;
            int c = wn * 32 + nf * 8 + qc;
            *(__nv_bfloat162*)&Eb[(size_t)r * NN + c] =
                __floats2bfloat162_rn(__expf(acc[mf][nf][0]), __expf(acc[mf][nf][1]));
            *(__nv_bfloat162*)&Eb[(size_t)(r + 8) * NN + c] =
                __floats2bfloat162_rn(__expf(acc[mf][nf][2]), __expf(acc[mf][nf][3]));
        }
    }
}

// ===========================================================================
// rowsum: R[b,i] = sum_j E[b,i,j]
// ===========================================================================
__global__ void rowsum_kernel(const __nv_bfloat16* __restrict__ E,
                              float* __restrict__ R)
{
    const int i = blockIdx.x, b = blockIdx.y;
    const uint4* row = (const uint4*)(E + ((size_t)b * NN + i) * NN);
    const int tid = threadIdx.x;
    __shared__ float red[8];

    float s = 0.0f;
    #pragma unroll
    for (int u = 0; u < 2; u++) {
        uint4 v = row[tid + u * 256];
        uint32_t w[4] = {v.x, v.y, v.z, v.w};
        #pragma unroll
        for (int q = 0; q < 4; q++) {
            float2 f = __bfloat1622float2(*(const __nv_bfloat162*)&w[q]);
            s += f.x + f.y;
        }
    }
    #pragma unroll
    for (int off = 16; off > 0; off >>= 1)
        s += __shfl_xor_sync(0xFFFFFFFFu, s, off);
    if ((tid & 31) == 0) red[tid >> 5] = s;
    __syncthreads();
    if (tid == 0) {
        float t = 0.0f;
        #pragma unroll
        for (int w2 = 0; w2 < 8; w2++) t += red[w2];
        R[(size_t)b * NN + i] = t;
    }
}

// ===========================================================================
// vscale: Vb[b,c,i] = bf16( f32(Vr[b,c,i]) / R[b,i] )
// ===========================================================================
__global__ void vscale_kernel(const __nv_bfloat16* __restrict__ Vr,
                              const float* __restrict__ R,
                              __nv_bfloat16* __restrict__ Vb)
{
    size_t idx = ((size_t)blockIdx.x * 256 + threadIdx.x) * 8;
    int i = (int)(idx & (NN - 1));
    int b = (int)(idx >> 20);                 // CO*NN = 2^20
    uint4 v = *(const uint4*)&Vr[idx];
    float4 r0 = *(const float4*)&R[(size_t)b * NN + i];
    float4 r1 = *(const float4*)&R[(size_t)b * NN + i + 4];
    float2 f0 = __bfloat1622float2(*(const __nv_bfloat162*)&v.x);
    float2 f1 = __bfloat1622float2(*(const __nv_bfloat162*)&v.y);
    float2 f2 = __bfloat1622float2(*(const __nv_bfloat162*)&v.z);
    float2 f3 = __bfloat1622float2(*(const __nv_bfloat162*)&v.w);
    uint2 o0 = pack4bf(f0.x / r0.x, f0.y / r0.y, f1.x / r0.z, f1.y / r0.w);
    uint2 o1 = pack4bf(f2.x / r1.x, f2.y / r1.y, f3.x / r1.z, f3.y / r1.w);
    uint4 o = make_uint4(o0.x, o0.y, o1.x, o1.y);
    *(uint4*)&Vb[idx] = o;
}

// ===========================================================================
// out_mma_d: out[b,c,j] = sum_i V'[b,c,i]*E[b,i,j] + xs2
// 256 threads, CTA 128(c) x 128(j). A direct b32; B ldmatrix.x2.trans.
// 3-stage cp.async pipeline.
// ===========================================================================
#define SBO_STRIDE 272                     // 128 bf16 (256B) + 16B pad
#define SBO_BYTES  (32 * SBO_STRIDE)       // 8704
#define O_STAGE    (SA_BYTES + SBO_BYTES)  // 18944
#define O_NSTAGE   3
#define O_SMEM     (O_NSTAGE * O_STAGE)    // 56832

__global__ void __launch_bounds__(256, 1)
out_mma_d(const __nv_bfloat16* __restrict__ V,
          const __nv_bfloat16* __restrict__ E,
          const float* __restrict__ xs2,
          float* __restrict__ out)
{
    extern __shared__ __align__(16) char sm[];
    const int tid = threadIdx.x, lane = tid & 31, wid = tid >> 5;
    const int b = blockIdx.z, c0 = blockIdx.y * 128, j0 = blockIdx.x * 128;
    const int wm = wid & 1, wn = wid >> 1;
    const int qr = lane >> 2;
    const int qk = (lane & 3) * 2;
    const int ln = lane & 15;

    const __nv_bfloat16* Ag = V + ((size_t)b * CO + c0) * NN;
    const __nv_bfloat16* Bg = E + (size_t)b * NN * NN + j0;
    const uint32_t sbase = smem_u32(sm);

    const int arow = tid >> 2, aseg = tid & 3;
    const int brow = tid >> 4, bseg = tid & 15;

    auto issue = [&](int ch, int st) {
        uint32_t sA = sbase + st * O_STAGE;
        uint32_t sB = sA + SA_BYTES;
        const __nv_bfloat16* a0 = Ag + ch * 32;
        const __nv_bfloat16* b0 = Bg + (size_t)(ch * 32) * NN;
        #pragma unroll
        for (int t = 0; t < 2; t++) {
            int ra = arow + t * 64;
            CP16(sA + (uint32_t)(ra * SA_STRIDE + aseg * 16),
                 a0 + (size_t)ra * NN + aseg * 8);
            int rb = brow + t * 16;
            CP16(sB + (uint32_t)(rb * SBO_STRIDE + bseg * 16),
                 b0 + (size_t)rb * NN + bseg * 8);
        }
        CP_COMMIT();
    };

    float acc[4][4][4] = {};
    issue(0, 0);
    issue(1, 1);
    issue(2, 2);

    const int NCH = NN / 32;   // 128
    int st = 0;
    #pragma unroll 1
    for (int ch = 0; ch < NCH; ch++) {
        if (ch < NCH - 2)       CP_WAITN(2);
        else if (ch == NCH - 2) CP_WAITN(1);
        else                    CP_WAITN(0);
        __syncthreads();
        const char* pA = sm + st * O_STAGE;
        const uint32_t sB32 = sbase + st * O_STAGE + SA_BYTES;
        #pragma unroll
        for (int ks = 0; ks < 2; ks++) {
            const int kbyteA = ks * 32 + qk * 2;
            const uint32_t brow_addr = sB32 + (uint32_t)((ks * 16 + ln) * SBO_STRIDE
                                                         + wn * 64);
            uint32_t a[4][4], bb[4][2];
            #pragma unroll
            for (int mf = 0; mf < 4; mf++) {
                int r = wm * 64 + mf * 16 + qr;
                const char* base = pA + r * SA_STRIDE + kbyteA;
                a[mf][0] = *(const uint32_t*)(base);
                a[mf][1] = *(const uint32_t*)(base + 8 * SA_STRIDE);
                a[mf][2] = *(const uint32_t*)(base + 16);
                a[mf][3] = *(const uint32_t*)(base + 8 * SA_STRIDE + 16);
            }
            #pragma unroll
            for (int nf = 0; nf < 4; nf++)
                LDSM2T(bb[nf][0], bb[nf][1], brow_addr + nf * 16);
            #pragma unroll
            for (int mf = 0; mf < 4; mf++)
                #pragma unroll
                for (int nf = 0; nf < 4; nf++)
                    MMA_BF16(acc[mf][nf], a[mf], bb[nf]);
        }
        __syncthreads();
        if (ch + 3 < NCH) issue(ch + 3, st);
        st = (st == O_NSTAGE - 1) ? 0 : st + 1;
    }

    const int qc = (lane & 3) * 2;
    const float* Xb = xs2 + ((size_t)b * CO + c0) * NN + j0;
    float* Ob = out + ((size_t)b * CO + c0) * NN + j0;
    #pragma unroll
    for (int mf = 0; mf < 4; mf++) {
        #pragma unroll
        for (int nf = 0; nf < 4; nf++) {
            int r = wm * 64 + mf * 16 + qr;
            int c = wn * 32 + nf * 8 + qc;
            float2 x0 = *(const float2*)&Xb[(size_t)r * NN + c];
            float2 x1 = *(const float2*)&Xb[(size_t)(r + 8) * NN + c];
            *(float2*)&Ob[(size_t)r * NN + c] =
                make_float2(acc[mf][nf][0] + x0.x, acc[mf][nf][1] + x0.y);
            *(float2*)&Ob[(size_t)(r + 8) * NN + c] =
                make_float2(acc[mf][nf][2] + x1.x, acc[mf][nf][3] + x1.y);
        }
    }
}

// ===========================================================================
// Projection (bf16 epilogue): Y[b,o,j] = bf16( sum_c W[o,c] X[b,c,j] + b[o] )
// ===========================================================================
template <int CIN>
__global__ void proj_kernel(const float* __restrict__ X,
                            const float* __restrict__ W,
                            const float* __restrict__ bias,
                            __nv_bfloat16* __restrict__ Y)
{
    const int b  = blockIdx.z;
    const int j0 = blockIdx.x * 64;
    const int m0 = blockIdx.y * 64;

    __shared__ float As[16][68];
    __shared__ float Bs[16][68];

    const int tid = threadIdx.x;
    const int tx = tid & 15;
    const int ty = tid >> 4;

    const float* Xb = X + (size_t)b * CIN * NN;
    float acc[4][4] = {};

    for (int k0 = 0; k0 < CIN; k0 += 16) {
        {
            int m  = tid >> 2;
            int kq = (tid & 3) * 4;
            float4 w4 = *(const float4*)&W[(size_t)(m0 + m) * CIN + k0 + kq];
            As[kq + 0][m] = w4.x; As[kq + 1][m] = w4.y;
            As[kq + 2][m] = w4.z; As[kq + 3][m] = w4.w;
        }
        {
            int k  = tid >> 4;
            int jq = (tid & 15) * 4;
            *(float4*)&Bs[k][jq] = *(const float4*)&Xb[(size_t)(k0 + k) * NN + j0 + jq];
        }
        __syncthreads();
        #pragma unroll
        for (int k = 0; k < 16; k++) {
            float4 a4 = *(const float4*)&As[k][ty * 4];
            float4 b4 = *(const float4*)&Bs[k][tx * 4];
            float a[4] = {a4.x, a4.y, a4.z, a4.w};
            float bv[4] = {b4.x, b4.y, b4.z, b4.w};
            #pragma unroll
            for (int i = 0; i < 4; i++)
                #pragma unroll
                for (int j = 0; j < 4; j++)
                    acc[i][j] += a[i] * bv[j];
        }
        __syncthreads();
    }

    __nv_bfloat16* Yb = Y + (size_t)b * CO * NN;
    #pragma unroll
    for (int i = 0; i < 4; i++) {
        int m = m0 + ty * 4 + i;
        float bs = bias[m];
        uint2 r = pack4bf(acc[i][0] + bs, acc[i][1] + bs,
                          acc[i][2] + bs, acc[i][3] + bs);
        *(uint2*)&Yb[(size_t)m * NN + j0 + tx * 4] = r;
    }
}

// ===========================================================================
// Tiled transpose + scale, bf16 in/out: Yt[b][n][c] = X[b][c][n]*scale
// ===========================================================================
__global__ void transpose_scale_bf16(const __nv_bfloat16* __restrict__ X,
                                     __nv_bfloat16* __restrict__ Yt,
                                     float scale)
{
    __shared__ float t[32][33];
    const int b  = blockIdx.z;
    const int n0 = blockIdx.x * 32;
    const int c0 = blockIdx.y * 32;
    const int tx = threadIdx.x, ty = threadIdx.y;

    const __nv_bfloat16* Xb = X + ((size_t)b * CO + c0) * NN + n0;
    #pragma unroll
    for (int k = 0; k < 4; k++) {
        int r = ty + k * 8;
        t[r][tx] = __bfloat162float(Xb[(size_t)r * NN + tx]);
    }
    __syncthreads();

    __nv_bfloat16* Yb = Yt + ((size_t)b * NN + n0) * CO + c0;
    #pragma unroll
    for (int k = 0; k < 4; k++) {
        int r = ty + k * 8;
        Yb[(size_t)r * CO + tx] = __float2bfloat16(t[tx][r] * scale);
    }
}

// ===========================================================================
extern "C" void kernel_launch(void* const* d_in, const int* in_sizes, int n_in,
                              void* d_out, int out_size)
{
    const float* x_s2  = (const float*)d_in[0];
    const float* x_dem = (const float*)d_in[1];
    const float* Wq    = (const float*)d_in[2];
    const float* bq    = (const float*)d_in[3];
    const float* Wk    = (const float*)d_in[4];
    const float* bk    = (const float*)d_in[5];
    const float* Wv    = (const float*)d_in[6];
    const float* bv    = (const float*)d_in[7];
    float* out = (float*)d_out;

    float* Rp;
    __nv_bfloat16 *Qb, *Kb, *Vr, *Qt, *Kt, *Vb, *Ep;
    cudaGetSymbolAddress((void**)&Qb, g_Qb);
    cudaGetSymbolAddress((void**)&Kb, g_Kb);
    cudaGetSymbolAddress((void**)&Vr, g_Vr);
    cudaGetSymbolAddress((void**)&Qt, g_Qt);
    cudaGetSymbolAddress((void**)&Kt, g_Kt);
    cudaGetSymbolAddress((void**)&Vb, g_Vb);
    cudaGetSymbolAddress((void**)&Ep, g_E);
    cudaGetSymbolAddress((void**)&Rp, g_R);

    cudaFuncSetAttribute(out_mma_d, cudaFuncAttributeMaxDynamicSharedMemorySize, O_SMEM);

    // One-time host-side stream/event setup (no device memory involved).
    static cudaStream_t s1 = nullptr, s2 = nullptr;
    static cudaEvent_t evRoot = nullptr, evK = nullptr, evV = nullptr;
    if (!s1) {
        cudaStreamCreateWithFlags(&s1, cudaStreamNonBlocking);
        cudaStreamCreateWithFlags(&s2, cudaStreamNonBlocking);
        cudaEventCreateWithFlags(&evRoot, cudaEventDisableTiming);
        cudaEventCreateWithFlags(&evK, cudaEventDisableTiming);
        cudaEventCreateWithFlags(&evV, cudaEventDisableTiming);
    }

    dim3 blk(256);
    dim3 grid_proj(NN / 64, CO / 64, BB);
    dim3 grid_tr(NN / 32, CO / 32, BB);
    dim3 blk_tr(32, 8);

    // Fork from the (capturing) default stream.
    cudaEventRecord(evRoot, 0);
    cudaStreamWaitEvent(s1, evRoot, 0);
    cudaStreamWaitEvent(s2, evRoot, 0);

    // Branch s1: K projection + transpose
    proj_kernel<CD><<<grid_proj, blk, 0, s1>>>(x_dem, Wk, bk, Kb);
    transpose_scale_bf16<<<grid_tr, blk_tr, 0, s1>>>(Kb, Kt, 1.0f);
    cudaEventRecord(evK, s1);

    // Branch s2: V projection
    proj_kernel<CD><<<grid_proj, blk, 0, s2>>>(x_dem, Wv, bv, Vr);
    cudaEventRecord(evV, s2);

    // Spine (default stream): Q projection + transpose
    proj_kernel<CS><<<grid_proj, blk>>>(x_s2, Wq, bq, Qb);
    transpose_scale_bf16<<<grid_tr, blk_tr>>>(Qb, Qt, SCALE);

    // Join K before s_mma
    cudaStreamWaitEvent(0, evK, 0);
    s_mma_d<<<dim3(NN / 128, NN / 128, BB), blk>>>(Kt, Qt, Ep);

    rowsum_kernel<<<dim3(NN, BB), blk>>>(Ep, Rp);

    // Join V before vscale
    cudaStreamWaitEvent(0, evV, 0);
    vscale_kernel<<<(unsigned)((size_t)BB * CO * NN / 2048), 256>>>(Vr, Rp, Vb);

    out_mma_d<<<dim3(NN / 128, CO / 128, BB), blk, O_SMEM>>>(Vb, Ep, x_s2, out);
}

// round 16
// speedup vs baseline: 1.3694x; 1.1658x over previous
#include <cuda_runtime.h>
#include <cuda_bf16.h>
#include <cstdint>

// CrossAttentionFusion: B=4, S2_CH=256, DEM_CH=64, OUT_CH=256, H=W=64, N=4096
#define BB 4
#define CS 256
#define CD 64
#define CO 256
#define NN 4096
#define SCALE 0.0625f

// Scratch (device globals: allocation-free rule)
__device__ __nv_bfloat16 g_Xs[(size_t)BB * CS * NN];   // x_s2 bf16 [b][c][n]
__device__ __nv_bfloat16 g_Xd[(size_t)BB * CD * NN];   // x_dem bf16 [b][c][n]
__device__ __nv_bfloat16 g_Wq[(size_t)CO * CS];        // Wq bf16
__device__ __nv_bfloat16 g_Wk[(size_t)CO * CD];        // Wk bf16
__device__ __nv_bfloat16 g_Wv[(size_t)CO * CD];        // Wv bf16
__device__ __nv_bfloat16 g_Qt[(size_t)BB * NN * CO];   // Q^T bf16 [b][j][c] (scale folded)
__device__ __nv_bfloat16 g_Kt[(size_t)BB * NN * CO];   // K^T bf16 [b][i][c]
__device__ __nv_bfloat16 g_Vr[(size_t)BB * CO * NN];   // V bf16 [b][c][i] (unscaled)
__device__ __nv_bfloat16 g_Vb[(size_t)BB * CO * NN];   // V' = V/R bf16 [b][c][i]
__device__ __nv_bfloat16 g_E [(size_t)BB * NN * NN];   // exp(logits) bf16 [b][i][j]
__device__ float         g_R [(size_t)BB * NN];        // row sums of E

// ===========================================================================
// helpers
// ===========================================================================
__device__ __forceinline__ uint32_t smem_u32(const void* p) {
    uint32_t a;
    asm("{ .reg .u64 t; cvta.to.shared.u64 t, %1; cvt.u32.u64 %0, t; }"
        : "=r"(a) : "l"(p));
    return a;
}

#define CP16(dst, src) \
    asm volatile("cp.async.cg.shared.global [%0], [%1], 16;" \
                 :: "r"(dst), "l"(src))
#define CP_COMMIT() asm volatile("cp.async.commit_group;" ::: "memory")
#define CP_WAITN(n) asm volatile("cp.async.wait_group %0;" :: "n"(n) : "memory")

#define LDSM2T(r0, r1, addr) \
    asm volatile("ldmatrix.sync.aligned.m8n8.x2.trans.shared.b16 {%0,%1}, [%2];" \
                 : "=r"(r0), "=r"(r1) : "r"(addr))

#define MMA_BF16(d, av, bv) \
    asm volatile("mma.sync.aligned.m16n8k16.row.col.f32.bf16.bf16.f32 " \
                 "{%0,%1,%2,%3}, {%4,%5,%6,%7}, {%8,%9}, {%0,%1,%2,%3};" \
                 : "+f"((d)[0]), "+f"((d)[1]), "+f"((d)[2]), "+f"((d)[3]) \
                 : "r"((av)[0]), "r"((av)[1]), "r"((av)[2]), "r"((av)[3]), \
                   "r"((bv)[0]), "r"((bv)[1]))

__device__ __forceinline__ uint2 pack4bf(float a, float b, float c, float d) {
    __nv_bfloat162 lo = __floats2bfloat162_rn(a, b);
    __nv_bfloat162 hi = __floats2bfloat162_rn(c, d);
    uint2 r;
    r.x = *(uint32_t*)&lo;
    r.y = *(uint32_t*)&hi;
    return r;
}

#define SA_STRIDE 80                       // 32 bf16 (64B) + 16B pad
#define SA_BYTES  (128 * SA_STRIDE)        // 10240
#define SBO_STRIDE 272                     // 128 bf16 (256B) + 16B pad
#define SBO_BYTES  (32 * SBO_STRIDE)       // 8704
#define P_STAGE   (SA_BYTES + SBO_BYTES)   // 18944

// ===========================================================================
// cvt: bf16(X) elementwise, 4 per thread
// ===========================================================================
__global__ void cvt_bf16_kernel(const float* __restrict__ X,
                                __nv_bfloat16* __restrict__ Y)
{
    size_t i = ((size_t)blockIdx.x * 256 + threadIdx.x) * 4;
    float4 v = *(const float4*)&X[i];
    *(uint2*)&Y[i] = pack4bf(v.x, v.y, v.z, v.w);
}

// ===========================================================================
// projT_mma: Yt[b,j,c] = ( sum_k X[b,k,j] * W[c,k] + bias[c] ) * scale
// A(j,k) = X^T via u16 gather from [k][j] tile; B(c,k) = W rows direct b32.
// CTA 128(j) x 128(c). warp tile 64(j) x 32(c).
// ===========================================================================
template <int CIN>
__global__ void __launch_bounds__(256, 1)
projT_mma(const __nv_bfloat16* __restrict__ X,
          const __nv_bfloat16* __restrict__ Wb,
          const float* __restrict__ bias,
          __nv_bfloat16* __restrict__ Yt, float scale)
{
    constexpr int NCH = CIN / 32;
    __shared__ __align__(16) char sm[2 * P_STAGE];
    const int tid = threadIdx.x, lane = tid & 31, wid = tid >> 5;
    const int b = blockIdx.z, j0 = blockIdx.x * 128, c0 = blockIdx.y * 128;
    const int wm = wid & 1, wn = wid >> 1;
    const int qr = lane >> 2;
    const int qk = (lane & 3) * 2;

    const __nv_bfloat16* Xb = X + (size_t)b * CIN * NN;
    const uint32_t sbase = smem_u32(sm);

    const int crow = tid >> 2, cseg = tid & 3;     // W: 128 rows x 4 segs (x2)
    const int brow = tid >> 4, bseg = tid & 15;    // X: 32 rows x 16 segs (x2)

    auto issue = [&](int ch, int st) {
        uint32_t sW = sbase + st * P_STAGE;
        uint32_t sX = sW + SA_BYTES;
        const int k0 = ch * 32;
        #pragma unroll
        for (int t = 0; t < 2; t++) {
            int rw = crow + t * 64;
            CP16(sW + (uint32_t)(rw * SA_STRIDE + cseg * 16),
                 Wb + (size_t)(c0 + rw) * CIN + k0 + cseg * 8);
            int rx = brow + t * 16;
            CP16(sX + (uint32_t)(rx * SBO_STRIDE + bseg * 16),
                 Xb + (size_t)(k0 + rx) * NN + j0 + bseg * 8);
        }
        CP_COMMIT();
    };

    float acc[4][4][4] = {};
    issue(0, 0);
    issue(1, 1);

    #pragma unroll 1
    for (int ch = 0; ch < NCH; ch++) {
        const int st = ch & 1;
        if (ch == NCH - 1) CP_WAITN(0); else CP_WAITN(1);
        __syncthreads();
        const char* pW = sm + st * P_STAGE;
        const char* pX = pW + SA_BYTES;
        #pragma unroll
        for (int ks = 0; ks < 2; ks++) {
            const int kbyte = qk * 2 + ks * 32;    // within W row (bf16*2)
            uint32_t a[4][4], bb[4][2];
            #pragma unroll
            for (int mf = 0; mf < 4; mf++) {
                int j = wm * 64 + mf * 16 + qr;    // j-local
                const char* colp = pX + (size_t)(ks * 16 + qk) * SBO_STRIDE + j * 2;
                uint32_t p0 = *(const uint16_t*)(colp);                    // (j, qk)
                uint32_t p1 = *(const uint16_t*)(colp + SBO_STRIDE);       // (j, qk+1)
                uint32_t p2 = *(const uint16_t*)(colp + 16);               // (j+8, qk)
                uint32_t p3 = *(const uint16_t*)(colp + SBO_STRIDE + 16);  // (j+8, qk+1)
                uint32_t p4 = *(const uint16_t*)(colp + 8 * SBO_STRIDE);       // (j, qk+8)
                uint32_t p5 = *(const uint16_t*)(colp + 9 * SBO_STRIDE);       // (j, qk+9)
                uint32_t p6 = *(const uint16_t*)(colp + 8 * SBO_STRIDE + 16);  // (j+8, qk+8)
                uint32_t p7 = *(const uint16_t*)(colp + 9 * SBO_STRIDE + 16);  // (j+8, qk+9)
                a[mf][0] = p0 | (p1 << 16);
                a[mf][1] = p2 | (p3 << 16);
                a[mf][2] = p4 | (p5 << 16);
                a[mf][3] = p6 | (p7 << 16);
            }
            #pragma unroll
            for (int nf = 0; nf < 4; nf++) {
                int n = wn * 32 + nf * 8 + qr;     // c-local
                const char* base = pW + n * SA_STRIDE + kbyte;
                bb[nf][0] = *(const uint32_t*)(base);
                bb[nf][1] = *(const uint32_t*)(base + 16);
            }
            #pragma unroll
            for (int mf = 0; mf < 4; mf++)
                #pragma unroll
                for (int nf = 0; nf < 4; nf++)
                    MMA_BF16(acc[mf][nf], a[mf], bb[nf]);
        }
        __syncthreads();
        if (ch + 2 < NCH) issue(ch + 2, st);
    }

    const int qc = (lane & 3) * 2;
    __nv_bfloat16* Yb = Yt + ((size_t)b * NN + j0) * CO + c0;
    #pragma unroll
    for (int mf = 0; mf < 4; mf++) {
        #pragma unroll
        for (int nf = 0; nf < 4; nf++) {
            int r = wm * 64 + mf * 16 + qr;       // j-local
            int c = wn * 32 + nf * 8 + qc;        // c-local
            float b0 = bias[c0 + c], b1 = bias[c0 + c + 1];
            *(__nv_bfloat162*)&Yb[(size_t)r * CO + c] =
                __floats2bfloat162_rn((acc[mf][nf][0] + b0) * scale,
                                      (acc[mf][nf][1] + b1) * scale);
            *(__nv_bfloat162*)&Yb[(size_t)(r + 8) * CO + c] =
                __floats2bfloat162_rn((acc[mf][nf][2] + b0) * scale,
                                      (acc[mf][nf][3] + b1) * scale);
        }
    }
}

// ===========================================================================
// projN_mma: Y[b,c,i] = sum_k W[c,k] * X[b,k,i] + bias[c]
// A(c,k) = W rows direct b32; B(k,i) via u16 gather from [k][i] tile.
// CTA 128(c) x 128(i).
// ===========================================================================
template <int CIN>
__global__ void __launch_bounds__(256, 1)
projN_mma(const __nv_bfloat16* __restrict__ X,
          const __nv_bfloat16* __restrict__ Wb,
          const float* __restrict__ bias,
          __nv_bfloat16* __restrict__ Y)
{
    constexpr int NCH = CIN / 32;
    __shared__ __align__(16) char sm[2 * P_STAGE];
    const int tid = threadIdx.x, lane = tid & 31, wid = tid >> 5;
    const int b = blockIdx.z, i0 = blockIdx.x * 128, c0 = blockIdx.y * 128;
    const int wm = wid & 1, wn = wid >> 1;
    const int qr = lane >> 2;
    const int qk = (lane & 3) * 2;

    const __nv_bfloat16* Xb = X + (size_t)b * CIN * NN;
    const uint32_t sbase = smem_u32(sm);

    const int crow = tid >> 2, cseg = tid & 3;
    const int brow = tid >> 4, bseg = tid & 15;

    auto issue = [&](int ch, int st) {
        uint32_t sW = sbase + st * P_STAGE;
        uint32_t sX = sW + SA_BYTES;
        const int k0 = ch * 32;
        #pragma unroll
        for (int t = 0; t < 2; t++) {
            int rw = crow + t * 64;
            CP16(sW + (uint32_t)(rw * SA_STRIDE + cseg * 16),
                 Wb + (size_t)(c0 + rw) * CIN + k0 + cseg * 8);
            int rx = brow + t * 16;
            CP16(sX + (uint32_t)(rx * SBO_STRIDE + bseg * 16),
                 Xb + (size_t)(k0 + rx) * NN + i0 + bseg * 8);
        }
        CP_COMMIT();
    };

    float acc[4][4][4] = {};
    issue(0, 0);
    issue(1, 1);

    #pragma unroll 1
    for (int ch = 0; ch < NCH; ch++) {
        const int st = ch & 1;
        if (ch == NCH - 1) CP_WAITN(0); else CP_WAITN(1);
        __syncthreads();
        const char* pW = sm + st * P_STAGE;
        const char* pX = pW + SA_BYTES;
        #pragma unroll
        for (int ks = 0; ks < 2; ks++) {
            const int kbyte = qk * 2 + ks * 32;
            uint32_t a[4][4], bb[4][2];
            #pragma unroll
            for (int mf = 0; mf < 4; mf++) {
                int r = wm * 64 + mf * 16 + qr;    // c-local
                const char* base = pW + r * SA_STRIDE + kbyte;
                a[mf][0] = *(const uint32_t*)(base);
                a[mf][1] = *(const uint32_t*)(base + 8 * SA_STRIDE);
                a[mf][2] = *(const uint32_t*)(base + 16);
                a[mf][3] = *(const uint32_t*)(base + 8 * SA_STRIDE + 16);
            }
            #pragma unroll
            for (int nf = 0; nf < 4; nf++) {
                int n = wn * 32 + nf * 8 + qr;     // i-local
                const char* colp = pX + (size_t)(ks * 16 + qk) * SBO_STRIDE + n * 2;
                uint32_t p0 = *(const uint16_t*)(colp);
                uint32_t p1 = *(const uint16_t*)(colp + SBO_STRIDE);
                uint32_t p2 = *(const uint16_t*)(colp + 8 * SBO_STRIDE);
                uint32_t p3 = *(const uint16_t*)(colp + 9 * SBO_STRIDE);
                bb[nf][0] = p0 | (p1 << 16);
                bb[nf][1] = p2 | (p3 << 16);
            }
            #pragma unroll
            for (int mf = 0; mf < 4; mf++)
                #pragma unroll
                for (int nf = 0; nf < 4; nf++)
                    MMA_BF16(acc[mf][nf], a[mf], bb[nf]);
        }
        __syncthreads();
        if (ch + 2 < NCH) issue(ch + 2, st);
    }

    const int qc = (lane & 3) * 2;
    __nv_bfloat16* Yb = Y + ((size_t)b * CO + c0) * NN + i0;
    #pragma unroll
    for (int mf = 0; mf < 4; mf++) {
        #pragma unroll
        for (int nf = 0; nf < 4; nf++) {
            int r = wm * 64 + mf * 16 + qr;        // c-local
            int c = wn * 32 + nf * 8 + qc;         // i-local
            float br0 = bias[c0 + r], br8 = bias[c0 + r + 8];
            *(__nv_bfloat162*)&Yb[(size_t)r * NN + c] =
                __floats2bfloat162_rn(acc[mf][nf][0] + br0, acc[mf][nf][1] + br0);
            *(__nv_bfloat162*)&Yb[(size_t)(r + 8) * NN + c] =
                __floats2bfloat162_rn(acc[mf][nf][2] + br8, acc[mf][nf][3] + br8);
        }
    }
}

// ===========================================================================
// s_mma_d: E[b,i,j] = exp( sum_c Kt[b,i,c] * Qt[b,j,c] )   (scale in Qt)
// (R12-proven.)
// ===========================================================================
#define S_STAGE   (2 * SA_BYTES)

__global__ void __launch_bounds__(256, 1)
s_mma_d(const __nv_bfloat16* __restrict__ Kt,
        const __nv_bfloat16* __restrict__ Qt,
        __nv_bfloat16* __restrict__ E)
{
    __shared__ __align__(16) char sm[2 * S_STAGE];   // 40 KB
    const int tid = threadIdx.x, lane = tid & 31, wid = tid >> 5;
    const int b = blockIdx.z, i0 = blockIdx.y * 128, j0 = blockIdx.x * 128;
    const int wm = wid & 1, wn = wid >> 1;
    const int qr = lane >> 2;
    const int qk = (lane & 3) * 2;

    const __nv_bfloat16* Ag = Kt + ((size_t)b * NN + i0) * CS;
    const __nv_bfloat16* Bg = Qt + ((size_t)b * NN + j0) * CS;
    const uint32_t sbase = smem_u32(sm);

    const int crow = tid >> 2, cseg = tid & 3;

    auto issue = [&](int ch, int st) {
        uint32_t sA = sbase + st * S_STAGE;
        uint32_t sB = sA + SA_BYTES;
        const __nv_bfloat16* a0 = Ag + ch * 32;
        const __nv_bfloat16* b0 = Bg + ch * 32;
        #pragma unroll
        for (int t = 0; t < 2; t++) {
            int row = crow + t * 64;
            uint32_t off = (uint32_t)(row * SA_STRIDE + cseg * 16);
            CP16(sA + off, a0 + (size_t)row * CS + cseg * 8);
            CP16(sB + off, b0 + (size_t)row * CS + cseg * 8);
        }
        CP_COMMIT();
    };

    float acc[4][4][4] = {};
    issue(0, 0);
    issue(1, 1);

    #pragma unroll 1
    for (int ch = 0; ch < 8; ch++) {
        const int st = ch & 1;
        if (ch == 7) CP_WAITN(0); else CP_WAITN(1);
        __syncthreads();
        const char* pA = sm + st * S_STAGE;
        const char* pB = pA + SA_BYTES;
        #pragma unroll
        for (int ks = 0; ks < 2; ks++) {
            const int kbyte = ks * 32 + qk * 2;
            uint32_t a[4][4], bb[4][2];
            #pragma unroll
            for (int mf = 0; mf < 4; mf++) {
                int r = wm * 64 + mf * 16 + qr;
                const char* base = pA + r * SA_STRIDE + kbyte;
                a[mf][0] = *(const uint32_t*)(base);
                a[mf][1] = *(const uint32_t*)(base + 8 * SA_STRIDE);
                a[mf][2] = *(const uint32_t*)(base + 16);
                a[mf][3] = *(const uint32_t*)(base + 8 * SA_STRIDE + 16);
            }
            #pragma unroll
            for (int nf = 0; nf < 4; nf++) {
                int n = wn * 32 + nf * 8 + qr;
                const char* base = pB + n * SA_STRIDE + kbyte;
                bb[nf][0] = *(const uint32_t*)(base);
                bb[nf][1] = *(const uint32_t*)(base + 16);
            }
            #pragma unroll
            for (int mf = 0; mf < 4; mf++)
                #pragma unroll
                for (int nf = 0; nf < 4; nf++)
                    MMA_BF16(acc[mf][nf], a[mf], bb[nf]);
        }
        __syncthreads();
        if (ch + 2 < 8) issue(ch + 2, st);
    }

    const int qc = (lane & 3) * 2;
    __nv_bfloat16* Eb = E + ((size_t)b * NN + i0) * NN + j0;
    #pragma unroll
    for (int mf = 0; mf < 4; mf++) {
        #pragma unroll
        for (int nf = 0; nf < 4; nf++) {
            int r = wm * 64 + mf * 16 + qr;
            int c = wn * 32 + nf * 8 + qc;
            *(__nv_bfloat162*)&Eb[(size_t)r * NN + c] =
                __floats2bfloat162_rn(__expf(acc[mf][nf][0]), __expf(acc[mf][nf][1]));
            *(__nv_bfloat162*)&Eb[(size_t)(r + 8) * NN + c] =
                __floats2bfloat162_rn(__expf(acc[mf][nf][2]), __expf(acc[mf][nf][3]));
        }
    }
}

// ===========================================================================
// rowsum: R[b,i] = sum_j E[b,i,j]
// ===========================================================================
__global__ void rowsum_kernel(const __nv_bfloat16* __restrict__ E,
                              float* __restrict__ R)
{
    const int i = blockIdx.x, b = blockIdx.y;
    const uint4* row = (const uint4*)(E + ((size_t)b * NN + i) * NN);
    const int tid = threadIdx.x;
    __shared__ float red[8];

    float s = 0.0f;
    #pragma unroll
    for (int u = 0; u < 2; u++) {
        uint4 v = row[tid + u * 256];
        uint32_t w[4] = {v.x, v.y, v.z, v.w};
        #pragma unroll
        for (int q = 0; q < 4; q++) {
            float2 f = __bfloat1622float2(*(const __nv_bfloat162*)&w[q]);
            s += f.x + f.y;
        }
    }
    #pragma unroll
    for (int off = 16; off > 0; off >>= 1)
        s += __shfl_xor_sync(0xFFFFFFFFu, s, off);
    if ((tid & 31) == 0) red[tid >> 5] = s;
    __syncthreads();
    if (tid == 0) {
        float t = 0.0f;
        #pragma unroll
        for (int w2 = 0; w2 < 8; w2++) t += red[w2];
        R[(size_t)b * NN + i] = t;
    }
}

// ===========================================================================
// vscale: Vb[b,c,i] = bf16( f32(Vr[b,c,i]) / R[b,i] )
// ===========================================================================
__global__ void vscale_kernel(const __nv_bfloat16* __restrict__ Vr,
                              const float* __restrict__ R,
                              __nv_bfloat16* __restrict__ Vb)
{
    size_t idx = ((size_t)blockIdx.x * 256 + threadIdx.x) * 8;
    int i = (int)(idx & (NN - 1));
    int b = (int)(idx >> 20);                 // CO*NN = 2^20
    uint4 v = *(const uint4*)&Vr[idx];
    float4 r0 = *(const float4*)&R[(size_t)b * NN + i];
    float4 r1 = *(const float4*)&R[(size_t)b * NN + i + 4];
    float2 f0 = __bfloat1622float2(*(const __nv_bfloat162*)&v.x);
    float2 f1 = __bfloat1622float2(*(const __nv_bfloat162*)&v.y);
    float2 f2 = __bfloat1622float2(*(const __nv_bfloat162*)&v.z);
    float2 f3 = __bfloat1622float2(*(const __nv_bfloat162*)&v.w);
    uint2 o0 = pack4bf(f0.x / r0.x, f0.y / r0.y, f1.x / r0.z, f1.y / r0.w);
    uint2 o1 = pack4bf(f2.x / r1.x, f2.y / r1.y, f3.x / r1.z, f3.y / r1.w);
    uint4 o = make_uint4(o0.x, o0.y, o1.x, o1.y);
    *(uint4*)&Vb[idx] = o;
}

// ===========================================================================
// out_mma_d: out[b,c,j] = sum_i V'[b,c,i]*E[b,i,j] + xs2
// 3-stage cp.async pipeline (R12-proven).
// ===========================================================================
#define O_STAGE    (SA_BYTES + SBO_BYTES)  // 18944
#define O_NSTAGE   3
#define O_SMEM     (O_NSTAGE * O_STAGE)    // 56832

__global__ void __launch_bounds__(256, 1)
out_mma_d(const __nv_bfloat16* __restrict__ V,
          const __nv_bfloat16* __restrict__ E,
          const float* __restrict__ xs2,
          float* __restrict__ out)
{
    extern __shared__ __align__(16) char sm[];
    const int tid = threadIdx.x, lane = tid & 31, wid = tid >> 5;
    const int b = blockIdx.z, c0 = blockIdx.y * 128, j0 = blockIdx.x * 128;
    const int wm = wid & 1, wn = wid >> 1;
    const int qr = lane >> 2;
    const int qk = (lane & 3) * 2;
    const int ln = lane & 15;

    const __nv_bfloat16* Ag = V + ((size_t)b * CO + c0) * NN;
    const __nv_bfloat16* Bg = E + (size_t)b * NN * NN + j0;
    const uint32_t sbase = smem_u32(sm);

    const int arow = tid >> 2, aseg = tid & 3;
    const int brow = tid >> 4, bseg = tid & 15;

    auto issue = [&](int ch, int st) {
        uint32_t sA = sbase + st * O_STAGE;
        uint32_t sB = sA + SA_BYTES;
        const __nv_bfloat16* a0 = Ag + ch * 32;
        const __nv_bfloat16* b0 = Bg + (size_t)(ch * 32) * NN;
        #pragma unroll
        for (int t = 0; t < 2; t++) {
            int ra = arow + t * 64;
            CP16(sA + (uint32_t)(ra * SA_STRIDE + aseg * 16),
                 a0 + (size_t)ra * NN + aseg * 8);
            int rb = brow + t * 16;
            CP16(sB + (uint32_t)(rb * SBO_STRIDE + bseg * 16),
                 b0 + (size_t)rb * NN + bseg * 8);
        }
        CP_COMMIT();
    };

    float acc[4][4][4] = {};
    issue(0, 0);
    issue(1, 1);
    issue(2, 2);

    const int NCH = NN / 32;   // 128
    int st = 0;
    #pragma unroll 1
    for (int ch = 0; ch < NCH; ch++) {
        if (ch < NCH - 2)       CP_WAITN(2);
        else if (ch == NCH - 2) CP_WAITN(1);
        else                    CP_WAITN(0);
        __syncthreads();
        const char* pA = sm + st * O_STAGE;
        const uint32_t sB32 = sbase + st * O_STAGE + SA_BYTES;
        #pragma unroll
        for (int ks = 0; ks < 2; ks++) {
            const int kbyteA = ks * 32 + qk * 2;
            const uint32_t brow_addr = sB32 + (uint32_t)((ks * 16 + ln) * SBO_STRIDE
                                                         + wn * 64);
            uint32_t a[4][4], bb[4][2];
            #pragma unroll
            for (int mf = 0; mf < 4; mf++) {
                int r = wm * 64 + mf * 16 + qr;
                const char* base = pA + r * SA_STRIDE + kbyteA;
                a[mf][0] = *(const uint32_t*)(base);
                a[mf][1] = *(const uint32_t*)(base + 8 * SA_STRIDE);
                a[mf][2] = *(const uint32_t*)(base + 16);
                a[mf][3] = *(const uint32_t*)(base + 8 * SA_STRIDE + 16);
            }
            #pragma unroll
            for (int nf = 0; nf < 4; nf++)
                LDSM2T(bb[nf][0], bb[nf][1], brow_addr + nf * 16);
            #pragma unroll
            for (int mf = 0; mf < 4; mf++)
                #pragma unroll
                for (int nf = 0; nf < 4; nf++)
                    MMA_BF16(acc[mf][nf], a[mf], bb[nf]);
        }
        __syncthreads();
        if (ch + 3 < NCH) issue(ch + 3, st);
        st = (st == O_NSTAGE - 1) ? 0 : st + 1;
    }

    const int qc = (lane & 3) * 2;
    const float* Xb = xs2 + ((size_t)b * CO + c0) * NN + j0;
    float* Ob = out + ((size_t)b * CO + c0) * NN + j0;
    #pragma unroll
    for (int mf = 0; mf < 4; mf++) {
        #pragma unroll
        for (int nf = 0; nf < 4; nf++) {
            int r = wm * 64 + mf * 16 + qr;
            int c = wn * 32 + nf * 8 + qc;
            float2 x0 = *(const float2*)&Xb[(size_t)r * NN + c];
            float2 x1 = *(const float2*)&Xb[(size_t)(r + 8) * NN + c];
            *(float2*)&Ob[(size_t)r * NN + c] =
                make_float2(acc[mf][nf][0] + x0.x, acc[mf][nf][1] + x0.y);
            *(float2*)&Ob[(size_t)(r + 8) * NN + c] =
                make_float2(acc[mf][nf][2] + x1.x, acc[mf][nf][3] + x1.y);
        }
    }
}

// ===========================================================================
extern "C" void kernel_launch(void* const* d_in, const int* in_sizes, int n_in,
                              void* d_out, int out_size)
{
    const float* x_s2  = (const float*)d_in[0];
    const float* x_dem = (const float*)d_in[1];
    const float* Wq    = (const float*)d_in[2];
    const float* bq    = (const float*)d_in[3];
    const float* Wk    = (const float*)d_in[4];
    const float* bk    = (const float*)d_in[5];
    const float* Wv    = (const float*)d_in[6];
    const float* bv    = (const float*)d_in[7];
    float* out = (float*)d_out;

    float* Rp;
    __nv_bfloat16 *Xs, *Xd, *Wqb, *Wkb, *Wvb, *Qt, *Kt, *Vr, *Vb, *Ep;
    cudaGetSymbolAddress((void**)&Xs, g_Xs);
    cudaGetSymbolAddress((void**)&Xd, g_Xd);
    cudaGetSymbolAddress((void**)&Wqb, g_Wq);
    cudaGetSymbolAddress((void**)&Wkb, g_Wk);
    cudaGetSymbolAddress((void**)&Wvb, g_Wv);
    cudaGetSymbolAddress((void**)&Qt, g_Qt);
    cudaGetSymbolAddress((void**)&Kt, g_Kt);
    cudaGetSymbolAddress((void**)&Vr, g_Vr);
    cudaGetSymbolAddress((void**)&Vb, g_Vb);
    cudaGetSymbolAddress((void**)&Ep, g_E);
    cudaGetSymbolAddress((void**)&Rp, g_R);

    cudaFuncSetAttribute(out_mma_d, cudaFuncAttributeMaxDynamicSharedMemorySize, O_SMEM);

    // One-time host-side stream/event setup (no device memory involved).
    static cudaStream_t s1 = nullptr, s2 = nullptr;
    static cudaEvent_t evRoot = nullptr, evXd = nullptr, evK = nullptr, evV = nullptr;
    if (!s1) {
        cudaStreamCreateWithFlags(&s1, cudaStreamNonBlocking);
        cudaStreamCreateWithFlags(&s2, cudaStreamNonBlocking);
        cudaEventCreateWithFlags(&evRoot, cudaEventDisableTiming);
        cudaEventCreateWithFlags(&evXd, cudaEventDisableTiming);
        cudaEventCreateWithFlags(&evK, cudaEventDisableTiming);
        cudaEventCreateWithFlags(&evV, cudaEventDisableTiming);
    }

    dim3 blk(256);
    dim3 grid_pt(NN / 128, CO / 128, BB);     // (32, 2, 4)

    // Fork from the (capturing) default stream.
    cudaEventRecord(evRoot, 0);
    cudaStreamWaitEvent(s1, evRoot, 0);
    cudaStreamWaitEvent(s2, evRoot, 0);

    // Branch s1: x_dem cvt, Wk cvt, K projection (transposed output)
    cvt_bf16_kernel<<<(unsigned)((size_t)BB * CD * NN / 1024), 256, 0, s1>>>(x_dem, Xd);
    cudaEventRecord(evXd, s1);
    cvt_bf16_kernel<<<CO * CD / 1024, 256, 0, s1>>>(Wk, Wkb);
    projT_mma<CD><<<grid_pt, blk, 0, s1>>>(Xd, Wkb, bk, Kt, 1.0f);
    cudaEventRecord(evK, s1);

    // Branch s2: Wv cvt, V projection (natural output); needs Xd from s1
    cvt_bf16_kernel<<<CO * CD / 1024, 256, 0, s2>>>(Wv, Wvb);
    cudaStreamWaitEvent(s2, evXd, 0);
    projN_mma<CD><<<grid_pt, blk, 0, s2>>>(Xd, Wvb, bv, Vr);
    cudaEventRecord(evV, s2);

    // Spine: x_s2 cvt, Wq cvt, Q projection (transposed, scale folded at epilogue)
    cvt_bf16_kernel<<<(unsigned)((size_t)BB * CS * NN / 1024), 256>>>(x_s2, Xs);
    cvt_bf16_kernel<<<CO * CS / 1024, 256>>>(Wq, Wqb);
    projT_mma<CS><<<grid_pt, blk>>>(Xs, Wqb, bq, Qt, SCALE);

    // Join K before s_mma
    cudaStreamWaitEvent(0, evK, 0);
    s_mma_d<<<dim3(NN / 128, NN / 128, BB), blk>>>(Kt, Qt, Ep);

    rowsum_kernel<<<dim3(NN, BB), blk>>>(Ep, Rp);

    // Join V before vscale
    cudaStreamWaitEvent(0, evV, 0);
    vscale_kernel<<<(unsigned)((size_t)BB * CO * NN / 2048), 256>>>(Vr, Rp, Vb);

    out_mma_d<<<dim3(NN / 128, CO / 128, BB), blk, O_SMEM>>>(Vb, Ep, x_s2, out);
}